// round 1
// baseline (speedup 1.0000x reference)
#include <cuda_runtime.h>
#include <math.h>

// Problem dims
#define S   2048
#define Dm  4096
#define HQ  32
#define HK  8
#define HD  128
#define NQ  (HQ*HD)   // 4096
#define NKV (HK*HD)   // 1024

// Scratch (device globals; no allocations allowed)
__device__ float g_Q[S*NQ];
__device__ float g_K[S*NKV];
__device__ float g_V[S*NKV];
__device__ float g_attn[S*NQ];

// ---------------------------------------------------------------------------
// SGEMM: C[M,N] = A[M,K] @ B[K,N], all row-major, fp32.
// 128x128 block tile, BK=8, 8x8 per thread, 256 threads. Dims assumed
// divisible (M%128==0, N%128==0, K%8==0) — true for all our shapes.
// ---------------------------------------------------------------------------
__global__ __launch_bounds__(256)
void sgemm_kernel(int M, int N, int K,
                  const float* __restrict__ A,
                  const float* __restrict__ B,
                  float* __restrict__ C) {
    __shared__ float As[8*128];   // transposed: As[k][m]
    __shared__ float Bs[8*128];   // Bs[k][n]

    const int bx = blockIdx.x;    // N tile
    const int by = blockIdx.y;    // M tile
    const int tid = threadIdx.x;

    const int threadCol = tid % 16;   // 16 cols * 8 = 128
    const int threadRow = tid / 16;   // 16 rows * 8 = 128

    // A load mapping: one float4 per thread. 128 rows x 2 float4/row.
    const int innerRowA = tid >> 1;          // 0..127
    const int innerColA = (tid & 1) * 4;     // 0 or 4
    // B load mapping: 8 rows x 32 float4/row.
    const int innerRowB = tid >> 5;          // 0..7
    const int innerColB = (tid & 31) * 4;    // 0..124

    const float* Ab = A + (size_t)(by*128) * K;
    const float* Bb = B + bx*128;
    float* Cb = C + (size_t)(by*128) * N + bx*128;

    float acc[8][8];
    #pragma unroll
    for (int i = 0; i < 8; i++)
        #pragma unroll
        for (int j = 0; j < 8; j++) acc[i][j] = 0.f;

    float regM[8], regN[8];

    for (int k0 = 0; k0 < K; k0 += 8) {
        // load A tile (transposed into As)
        float4 a4 = *(const float4*)&Ab[(size_t)innerRowA * K + k0 + innerColA];
        As[(innerColA + 0)*128 + innerRowA] = a4.x;
        As[(innerColA + 1)*128 + innerRowA] = a4.y;
        As[(innerColA + 2)*128 + innerRowA] = a4.z;
        As[(innerColA + 3)*128 + innerRowA] = a4.w;
        // load B tile
        *(float4*)&Bs[innerRowB*128 + innerColB] =
            *(const float4*)&Bb[(size_t)(k0 + innerRowB) * N + innerColB];
        __syncthreads();

        #pragma unroll
        for (int dot = 0; dot < 8; dot++) {
            #pragma unroll
            for (int i = 0; i < 8; i++) regM[i] = As[dot*128 + threadRow*8 + i];
            #pragma unroll
            for (int j = 0; j < 8; j++) regN[j] = Bs[dot*128 + threadCol*8 + j];
            #pragma unroll
            for (int i = 0; i < 8; i++)
                #pragma unroll
                for (int j = 0; j < 8; j++)
                    acc[i][j] = fmaf(regM[i], regN[j], acc[i][j]);
        }
        __syncthreads();
    }

    #pragma unroll
    for (int i = 0; i < 8; i++) {
        #pragma unroll
        for (int j4 = 0; j4 < 8; j4 += 4) {
            float4 v;
            v.x = acc[i][j4+0]; v.y = acc[i][j4+1];
            v.z = acc[i][j4+2]; v.w = acc[i][j4+3];
            *(float4*)&Cb[(size_t)(threadRow*8 + i) * N + threadCol*8 + j4] = v;
        }
    }
}

// ---------------------------------------------------------------------------
// RoPE (interleaved pairs), in place on T with layout [S, H, HD].
// ---------------------------------------------------------------------------
__global__ void rope_kernel(float* __restrict__ T,
                            const float* __restrict__ fc,
                            const float* __restrict__ fs,
                            int H) {
    int idx = blockIdx.x * blockDim.x + threadIdx.x;
    int total = S * H * (HD/2);
    if (idx >= total) return;
    int i = idx & 63;                 // pair index 0..63
    int h = (idx >> 6) % H;
    int s = idx / (64 * H);
    float c  = fc[s*64 + i];
    float sn = fs[s*64 + i];
    float* p = T + (size_t)s * H * HD + h * HD + 2*i;
    float t0 = p[0], t1 = p[1];
    p[0] = t0*c - t1*sn;
    p[1] = t0*sn + t1*c;
}

// ---------------------------------------------------------------------------
// Flash attention, fp32, causal, GQA (4 Q heads per KV head).
// Grid: (32 q-blocks of 64, 32 heads). 256 threads.
// Thread (ql = tid>>2, c = tid&3): query row ql, dim chunk c*32..c*32+31.
// ---------------------------------------------------------------------------
__global__ __launch_bounds__(256)
void flash_kernel(const float* __restrict__ Q,
                  const float* __restrict__ K,
                  const float* __restrict__ V,
                  float* __restrict__ O) {
    __shared__ float Ks[32*128];
    __shared__ float Vs[32*128];

    const int qb  = blockIdx.x;
    const int h   = blockIdx.y;
    const int kh  = h >> 2;
    const int tid = threadIdx.x;
    const int ql  = tid >> 2;
    const int c   = tid & 3;
    const int qg  = qb*64 + ql;
    const float scale = 0.08838834764831845f; // 1/sqrt(128)

    float q_reg[32], o_reg[32];
    #pragma unroll
    for (int d = 0; d < 32; d++) {
        q_reg[d] = Q[(size_t)qg*NQ + h*HD + c*32 + d];
        o_reg[d] = 0.f;
    }
    float m = -INFINITY, l = 0.f;

    const int nkv = qb*2 + 2;   // causal: only KV blocks covering keys <= qb*64+63
    for (int kb = 0; kb < nkv; kb++) {
        const int kv0 = kb * 32;
        __syncthreads();
        #pragma unroll
        for (int i = 0; i < 4; i++) {
            int e   = tid + i*256;        // float4 index 0..1023
            int row = e >> 5;
            int col = (e & 31) << 2;
            *(float4*)&Ks[row*128 + col] =
                *(const float4*)&K[(size_t)(kv0+row)*NKV + kh*HD + col];
            *(float4*)&Vs[row*128 + col] =
                *(const float4*)&V[(size_t)(kv0+row)*NKV + kh*HD + col];
        }
        __syncthreads();

        float s_reg[32];
        #pragma unroll
        for (int j = 0; j < 32; j++) {
            float p = 0.f;
            #pragma unroll
            for (int d = 0; d < 32; d++)
                p = fmaf(q_reg[d], Ks[j*128 + c*32 + d], p);
            p += __shfl_xor_sync(0xffffffffu, p, 1);
            p += __shfl_xor_sync(0xffffffffu, p, 2);
            s_reg[j] = (kv0 + j <= qg) ? p * scale : -INFINITY;
        }

        float bm = m;
        #pragma unroll
        for (int j = 0; j < 32; j++) bm = fmaxf(bm, s_reg[j]);
        float alpha = __expf(m - bm);     // m=-inf on first block -> alpha=0
        m = bm;

        float lsum = 0.f;
        #pragma unroll
        for (int j = 0; j < 32; j++) {
            float p = __expf(s_reg[j] - bm);
            s_reg[j] = p;
            lsum += p;
        }
        l = l*alpha + lsum;

        #pragma unroll
        for (int d = 0; d < 32; d++) o_reg[d] *= alpha;
        #pragma unroll
        for (int j = 0; j < 32; j++) {
            float p = s_reg[j];
            #pragma unroll
            for (int d = 0; d < 32; d++)
                o_reg[d] = fmaf(p, Vs[j*128 + c*32 + d], o_reg[d]);
        }
    }

    float inv_l = 1.f / l;
    #pragma unroll
    for (int d = 0; d < 32; d++)
        O[(size_t)qg*NQ + h*HD + c*32 + d] = o_reg[d] * inv_l;
}

// ---------------------------------------------------------------------------
// Launch
// ---------------------------------------------------------------------------
extern "C" void kernel_launch(void* const* d_in, const int* in_sizes, int n_in,
                              void* d_out, int out_size) {
    const float* x  = (const float*)d_in[0];
    const float* fc = (const float*)d_in[1];
    const float* fs = (const float*)d_in[2];
    const float* wq = (const float*)d_in[3];
    const float* wk = (const float*)d_in[4];
    const float* wv = (const float*)d_in[5];
    const float* wo = (const float*)d_in[6];
    float* out = (float*)d_out;

    float *Q, *K, *V, *ATT;
    cudaGetSymbolAddress((void**)&Q,   g_Q);
    cudaGetSymbolAddress((void**)&K,   g_K);
    cudaGetSymbolAddress((void**)&V,   g_V);
    cudaGetSymbolAddress((void**)&ATT, g_attn);

    // QKV projections
    sgemm_kernel<<<dim3(NQ/128,  S/128), 256>>>(S, NQ,  Dm, x, wq, Q);
    sgemm_kernel<<<dim3(NKV/128, S/128), 256>>>(S, NKV, Dm, x, wk, K);
    sgemm_kernel<<<dim3(NKV/128, S/128), 256>>>(S, NKV, Dm, x, wv, V);

    // RoPE on Q and K
    {
        int tq = S*HQ*(HD/2);
        rope_kernel<<<(tq + 255)/256, 256>>>(Q, fc, fs, HQ);
        int tk = S*HK*(HD/2);
        rope_kernel<<<(tk + 255)/256, 256>>>(K, fc, fs, HK);
    }

    // Causal GQA attention
    flash_kernel<<<dim3(S/64, HQ), 256>>>(Q, K, V, ATT);

    // Output projection
    sgemm_kernel<<<dim3(Dm/128, S/128), 256>>>(S, Dm, NQ, ATT, wo, out);
}

// round 2
// speedup vs baseline: 1.3252x; 1.3252x over previous
#include <cuda_runtime.h>
#include <math.h>

// Problem dims
#define S   2048
#define Dm  4096
#define HQ  32
#define HK  8
#define HD  128
#define NQ  (HQ*HD)   // 4096
#define NKV (HK*HD)   // 1024

// Scratch (device globals; no allocations allowed)
__device__ float g_Q[S*NQ];
__device__ float g_K[S*NKV];
__device__ float g_V[S*NKV];
__device__ float g_attn[S*NQ];

__device__ __forceinline__ unsigned f2tf32(float f) {
    unsigned r;
    asm("cvt.rna.tf32.f32 %0, %1;" : "=r"(r) : "f"(f));
    return r;
}

// ---------------------------------------------------------------------------
// tf32 tensor-core GEMM: C[M,N] = A[M,K] @ B[K,N], row-major fp32 in/out.
// 128x128 CTA tile, BK=16, double-buffered. 8 warps, each 64(M)x32(N).
// mma.sync.aligned.m16n8k8.row.col.f32.tf32.tf32.f32
// Requires M%128==0, N%128==0, K%16==0 (true for all shapes here).
// ---------------------------------------------------------------------------
#define PITCH 136   // floats per smem row; bank = 8*tig + gid -> conflict-free frags

__global__ __launch_bounds__(256)
void gemm_tf32(int M, int N, int K,
               const float* __restrict__ A,
               const float* __restrict__ B,
               float* __restrict__ C) {
    __shared__ __align__(16) float As[2][16][PITCH];  // [k][m], tf32 bits
    __shared__ __align__(16) float Bs[2][16][PITCH];  // [k][n], tf32 bits

    const int tid  = threadIdx.x;
    const int lane = tid & 31;
    const int wid  = tid >> 5;
    const int gid  = lane >> 2;   // group id (0..7)
    const int tig  = lane & 3;    // thread in group (0..3)
    const int warpM = wid >> 2;   // 0..1
    const int warpN = wid & 3;    // 0..3

    const int bx = blockIdx.x;    // N tile
    const int by = blockIdx.y;    // M tile

    // Global load mapping: A tile 128x16 -> each thread 8 consecutive floats.
    const int aRow = tid >> 1;          // 0..127
    const int aCol = (tid & 1) * 8;     // 0 or 8
    // B tile 16x128 -> each thread 8 consecutive floats.
    const int bRow = tid >> 4;          // 0..15
    const int bCol = (tid & 15) * 8;    // 0..120

    const float* Ab = A + (size_t)(by*128 + aRow) * K + aCol;
    const float* Bb = B + (size_t)bRow * N + bx*128 + bCol;

    float c[4][4][4];
    #pragma unroll
    for (int i = 0; i < 4; i++)
        #pragma unroll
        for (int j = 0; j < 4; j++)
            #pragma unroll
            for (int r = 0; r < 4; r++) c[i][j][r] = 0.f;

    const int nt = K / 16;

    float4 pa[2], pb[2];
    // preload tile 0
    pa[0] = *(const float4*)&Ab[0];
    pa[1] = *(const float4*)&Ab[4];
    pb[0] = *(const float4*)&Bb[0];
    pb[1] = *(const float4*)&Bb[4];

    // store tile 0 into buf 0
    {
        const float* av = (const float*)pa;
        #pragma unroll
        for (int e = 0; e < 8; e++)
            As[0][aCol + e][aRow] = __uint_as_float(f2tf32(av[e]));
        const float* bv = (const float*)pb;
        #pragma unroll
        for (int e = 0; e < 8; e++)
            Bs[0][bRow][bCol + e] = __uint_as_float(f2tf32(bv[e]));
    }
    __syncthreads();

    int buf = 0;
    for (int t = 0; t < nt; t++) {
        // prefetch next tile
        if (t + 1 < nt) {
            const float* An = Ab + (t+1)*16;
            const float* Bn = Bb + (size_t)(t+1)*16 * N;
            pa[0] = *(const float4*)&An[0];
            pa[1] = *(const float4*)&An[4];
            pb[0] = *(const float4*)&Bn[0];
            pb[1] = *(const float4*)&Bn[4];
        }

        // compute on current buffer
        #pragma unroll
        for (int ks = 0; ks < 16; ks += 8) {
            unsigned af[4][4], bf[4][2];
            #pragma unroll
            for (int mf = 0; mf < 4; mf++) {
                int m0 = warpM*64 + mf*16;
                af[mf][0] = __float_as_uint(As[buf][ks+tig  ][m0+gid  ]);
                af[mf][1] = __float_as_uint(As[buf][ks+tig  ][m0+gid+8]);
                af[mf][2] = __float_as_uint(As[buf][ks+tig+4][m0+gid  ]);
                af[mf][3] = __float_as_uint(As[buf][ks+tig+4][m0+gid+8]);
            }
            #pragma unroll
            for (int nf = 0; nf < 4; nf++) {
                int n0 = warpN*32 + nf*8;
                bf[nf][0] = __float_as_uint(Bs[buf][ks+tig  ][n0+gid]);
                bf[nf][1] = __float_as_uint(Bs[buf][ks+tig+4][n0+gid]);
            }
            #pragma unroll
            for (int mf = 0; mf < 4; mf++)
                #pragma unroll
                for (int nf = 0; nf < 4; nf++) {
                    asm volatile(
                        "mma.sync.aligned.m16n8k8.row.col.f32.tf32.tf32.f32 "
                        "{%0,%1,%2,%3}, {%4,%5,%6,%7}, {%8,%9}, {%0,%1,%2,%3};"
                        : "+f"(c[mf][nf][0]), "+f"(c[mf][nf][1]),
                          "+f"(c[mf][nf][2]), "+f"(c[mf][nf][3])
                        : "r"(af[mf][0]), "r"(af[mf][1]),
                          "r"(af[mf][2]), "r"(af[mf][3]),
                          "r"(bf[nf][0]), "r"(bf[nf][1]));
                }
        }

        // store prefetched tile
        if (t + 1 < nt) {
            int nb = buf ^ 1;
            const float* av = (const float*)pa;
            #pragma unroll
            for (int e = 0; e < 8; e++)
                As[nb][aCol + e][aRow] = __uint_as_float(f2tf32(av[e]));
            const float* bv = (const float*)pb;
            #pragma unroll
            for (int e = 0; e < 8; e++)
                Bs[nb][bRow][bCol + e] = __uint_as_float(f2tf32(bv[e]));
            __syncthreads();
            buf = nb;
        }
    }

    // epilogue
    #pragma unroll
    for (int mf = 0; mf < 4; mf++) {
        int row0 = by*128 + warpM*64 + mf*16 + gid;
        #pragma unroll
        for (int nf = 0; nf < 4; nf++) {
            int col = bx*128 + warpN*32 + nf*8 + tig*2;
            float2 v01 = make_float2(c[mf][nf][0], c[mf][nf][1]);
            float2 v23 = make_float2(c[mf][nf][2], c[mf][nf][3]);
            *(float2*)&C[(size_t)row0 * N + col]       = v01;
            *(float2*)&C[(size_t)(row0+8) * N + col]   = v23;
        }
    }
}

// ---------------------------------------------------------------------------
// RoPE (interleaved pairs), in place on T with layout [S, H, HD].
// ---------------------------------------------------------------------------
__global__ void rope_kernel(float* __restrict__ T,
                            const float* __restrict__ fc,
                            const float* __restrict__ fs,
                            int H) {
    int idx = blockIdx.x * blockDim.x + threadIdx.x;
    int total = S * H * (HD/2);
    if (idx >= total) return;
    int i = idx & 63;                 // pair index 0..63
    int h = (idx >> 6) % H;
    int s = idx / (64 * H);
    float c  = fc[s*64 + i];
    float sn = fs[s*64 + i];
    float* p = T + (size_t)s * H * HD + h * HD + 2*i;
    float t0 = p[0], t1 = p[1];
    p[0] = t0*c - t1*sn;
    p[1] = t0*sn + t1*c;
}

// ---------------------------------------------------------------------------
// Flash attention, fp32, causal, GQA (4 Q heads per KV head).
// Grid: (32 q-blocks of 64, 32 heads). 256 threads.
// ---------------------------------------------------------------------------
__global__ __launch_bounds__(256)
void flash_kernel(const float* __restrict__ Q,
                  const float* __restrict__ K,
                  const float* __restrict__ V,
                  float* __restrict__ O) {
    __shared__ float Ks[32*128];
    __shared__ float Vs[32*128];

    const int qb  = blockIdx.x;
    const int h   = blockIdx.y;
    const int kh  = h >> 2;
    const int tid = threadIdx.x;
    const int ql  = tid >> 2;
    const int c   = tid & 3;
    const int qg  = qb*64 + ql;
    const float scale = 0.08838834764831845f; // 1/sqrt(128)

    float q_reg[32], o_reg[32];
    #pragma unroll
    for (int d = 0; d < 32; d++) {
        q_reg[d] = Q[(size_t)qg*NQ + h*HD + c*32 + d];
        o_reg[d] = 0.f;
    }
    float m = -INFINITY, l = 0.f;

    const int nkv = qb*2 + 2;
    for (int kb = 0; kb < nkv; kb++) {
        const int kv0 = kb * 32;
        __syncthreads();
        #pragma unroll
        for (int i = 0; i < 4; i++) {
            int e   = tid + i*256;
            int row = e >> 5;
            int col = (e & 31) << 2;
            *(float4*)&Ks[row*128 + col] =
                *(const float4*)&K[(size_t)(kv0+row)*NKV + kh*HD + col];
            *(float4*)&Vs[row*128 + col] =
                *(const float4*)&V[(size_t)(kv0+row)*NKV + kh*HD + col];
        }
        __syncthreads();

        float s_reg[32];
        #pragma unroll
        for (int j = 0; j < 32; j++) {
            float p = 0.f;
            #pragma unroll
            for (int d = 0; d < 32; d++)
                p = fmaf(q_reg[d], Ks[j*128 + c*32 + d], p);
            p += __shfl_xor_sync(0xffffffffu, p, 1);
            p += __shfl_xor_sync(0xffffffffu, p, 2);
            s_reg[j] = (kv0 + j <= qg) ? p * scale : -INFINITY;
        }

        float bm = m;
        #pragma unroll
        for (int j = 0; j < 32; j++) bm = fmaxf(bm, s_reg[j]);
        float alpha = __expf(m - bm);
        m = bm;

        float lsum = 0.f;
        #pragma unroll
        for (int j = 0; j < 32; j++) {
            float p = __expf(s_reg[j] - bm);
            s_reg[j] = p;
            lsum += p;
        }
        l = l*alpha + lsum;

        #pragma unroll
        for (int d = 0; d < 32; d++) o_reg[d] *= alpha;
        #pragma unroll
        for (int j = 0; j < 32; j++) {
            float p = s_reg[j];
            #pragma unroll
            for (int d = 0; d < 32; d++)
                o_reg[d] = fmaf(p, Vs[j*128 + c*32 + d], o_reg[d]);
        }
    }

    float inv_l = 1.f / l;
    #pragma unroll
    for (int d = 0; d < 32; d++)
        O[(size_t)qg*NQ + h*HD + c*32 + d] = o_reg[d] * inv_l;
}

// ---------------------------------------------------------------------------
// Launch
// ---------------------------------------------------------------------------
extern "C" void kernel_launch(void* const* d_in, const int* in_sizes, int n_in,
                              void* d_out, int out_size) {
    const float* x  = (const float*)d_in[0];
    const float* fc = (const float*)d_in[1];
    const float* fs = (const float*)d_in[2];
    const float* wq = (const float*)d_in[3];
    const float* wk = (const float*)d_in[4];
    const float* wv = (const float*)d_in[5];
    const float* wo = (const float*)d_in[6];
    float* out = (float*)d_out;

    float *Q, *K, *V, *ATT;
    cudaGetSymbolAddress((void**)&Q,   g_Q);
    cudaGetSymbolAddress((void**)&K,   g_K);
    cudaGetSymbolAddress((void**)&V,   g_V);
    cudaGetSymbolAddress((void**)&ATT, g_attn);

    // QKV projections (tf32 tensor cores)
    gemm_tf32<<<dim3(NQ/128,  S/128), 256>>>(S, NQ,  Dm, x, wq, Q);
    gemm_tf32<<<dim3(NKV/128, S/128), 256>>>(S, NKV, Dm, x, wk, K);
    gemm_tf32<<<dim3(NKV/128, S/128), 256>>>(S, NKV, Dm, x, wv, V);

    // RoPE on Q and K
    {
        int tq = S*HQ*(HD/2);
        rope_kernel<<<(tq + 255)/256, 256>>>(Q, fc, fs, HQ);
        int tk = S*HK*(HD/2);
        rope_kernel<<<(tk + 255)/256, 256>>>(K, fc, fs, HK);
    }

    // Causal GQA attention
    flash_kernel<<<dim3(S/64, HQ), 256>>>(Q, K, V, ATT);

    // Output projection
    gemm_tf32<<<dim3(Dm/128, S/128), 256>>>(S, Dm, NQ, ATT, wo, out);
}

// round 3
// speedup vs baseline: 6.3716x; 4.8080x over previous
#include <cuda_runtime.h>
#include <math.h>
#include <stdint.h>

// Problem dims
#define S   2048
#define Dm  4096
#define HQ  32
#define HK  8
#define HD  128
#define NQ  (HQ*HD)   // 4096
#define NKV (HK*HD)   // 1024

// Scratch (device globals; no allocations allowed)
__device__ float g_Q[S*NQ];
__device__ float g_K[S*NKV];
__device__ float g_V[S*NKV];
__device__ float g_attn[S*NQ];

__device__ __forceinline__ unsigned f2tf32(float f) {
    unsigned r;
    asm("cvt.rna.tf32.f32 %0, %1;" : "=r"(r) : "f"(f));
    return r;
}

__device__ __forceinline__ void mma_tf32(float c[4], const unsigned a[4],
                                         unsigned b0, unsigned b1) {
    asm volatile(
        "mma.sync.aligned.m16n8k8.row.col.f32.tf32.tf32.f32 "
        "{%0,%1,%2,%3}, {%4,%5,%6,%7}, {%8,%9}, {%0,%1,%2,%3};"
        : "+f"(c[0]), "+f"(c[1]), "+f"(c[2]), "+f"(c[3])
        : "r"(a[0]), "r"(a[1]), "r"(a[2]), "r"(a[3]), "r"(b0), "r"(b1));
}

__device__ __forceinline__ void cp16(uint32_t dst, const void* src) {
    asm volatile("cp.async.cg.shared.global [%0], [%1], 16;\n" :: "r"(dst), "l"(src));
}
__device__ __forceinline__ void cp_commit() {
    asm volatile("cp.async.commit_group;\n");
}
template<int N> __device__ __forceinline__ void cp_wait() {
    asm volatile("cp.async.wait_group %0;\n" :: "n"(N));
}

// ---------------------------------------------------------------------------
// tf32 tensor-core GEMM: C[M,N] = A[M,K] @ B[K,N], row-major fp32 in/out.
// 128x128 CTA tile, BK=16, double-buffered. cvtOut: round output to tf32.
// ---------------------------------------------------------------------------
#define PITCH 136

__global__ __launch_bounds__(256)
void gemm_tf32(int M, int N, int K,
               const float* __restrict__ A,
               const float* __restrict__ B,
               float* __restrict__ C, int cvtOut) {
    __shared__ __align__(16) float As[2][16][PITCH];
    __shared__ __align__(16) float Bs[2][16][PITCH];

    const int tid  = threadIdx.x;
    const int lane = tid & 31;
    const int wid  = tid >> 5;
    const int gid  = lane >> 2;
    const int tig  = lane & 3;
    const int warpM = wid >> 2;
    const int warpN = wid & 3;

    const int bx = blockIdx.x;
    const int by = blockIdx.y;

    const int aRow = tid >> 1;
    const int aCol = (tid & 1) * 8;
    const int bRow = tid >> 4;
    const int bCol = (tid & 15) * 8;

    const float* Ab = A + (size_t)(by*128 + aRow) * K + aCol;
    const float* Bb = B + (size_t)bRow * N + bx*128 + bCol;

    float c[4][4][4];
    #pragma unroll
    for (int i = 0; i < 4; i++)
        #pragma unroll
        for (int j = 0; j < 4; j++)
            #pragma unroll
            for (int r = 0; r < 4; r++) c[i][j][r] = 0.f;

    const int nt = K / 16;

    float4 pa[2], pb[2];
    pa[0] = *(const float4*)&Ab[0];
    pa[1] = *(const float4*)&Ab[4];
    pb[0] = *(const float4*)&Bb[0];
    pb[1] = *(const float4*)&Bb[4];

    {
        const float* av = (const float*)pa;
        #pragma unroll
        for (int e = 0; e < 8; e++)
            As[0][aCol + e][aRow] = __uint_as_float(f2tf32(av[e]));
        const float* bv = (const float*)pb;
        #pragma unroll
        for (int e = 0; e < 8; e++)
            Bs[0][bRow][bCol + e] = __uint_as_float(f2tf32(bv[e]));
    }
    __syncthreads();

    int buf = 0;
    for (int t = 0; t < nt; t++) {
        if (t + 1 < nt) {
            const float* An = Ab + (t+1)*16;
            const float* Bn = Bb + (size_t)(t+1)*16 * N;
            pa[0] = *(const float4*)&An[0];
            pa[1] = *(const float4*)&An[4];
            pb[0] = *(const float4*)&Bn[0];
            pb[1] = *(const float4*)&Bn[4];
        }

        #pragma unroll
        for (int ks = 0; ks < 16; ks += 8) {
            unsigned af[4][4], bf[4][2];
            #pragma unroll
            for (int mf = 0; mf < 4; mf++) {
                int m0 = warpM*64 + mf*16;
                af[mf][0] = __float_as_uint(As[buf][ks+tig  ][m0+gid  ]);
                af[mf][1] = __float_as_uint(As[buf][ks+tig  ][m0+gid+8]);
                af[mf][2] = __float_as_uint(As[buf][ks+tig+4][m0+gid  ]);
                af[mf][3] = __float_as_uint(As[buf][ks+tig+4][m0+gid+8]);
            }
            #pragma unroll
            for (int nf = 0; nf < 4; nf++) {
                int n0 = warpN*32 + nf*8;
                bf[nf][0] = __float_as_uint(Bs[buf][ks+tig  ][n0+gid]);
                bf[nf][1] = __float_as_uint(Bs[buf][ks+tig+4][n0+gid]);
            }
            #pragma unroll
            for (int mf = 0; mf < 4; mf++)
                #pragma unroll
                for (int nf = 0; nf < 4; nf++)
                    mma_tf32(c[mf][nf], af[mf], bf[nf][0], bf[nf][1]);
        }

        if (t + 1 < nt) {
            int nb = buf ^ 1;
            const float* av = (const float*)pa;
            #pragma unroll
            for (int e = 0; e < 8; e++)
                As[nb][aCol + e][aRow] = __uint_as_float(f2tf32(av[e]));
            const float* bv = (const float*)pb;
            #pragma unroll
            for (int e = 0; e < 8; e++)
                Bs[nb][bRow][bCol + e] = __uint_as_float(f2tf32(bv[e]));
            __syncthreads();
            buf = nb;
        }
    }

    #pragma unroll
    for (int mf = 0; mf < 4; mf++) {
        int row0 = by*128 + warpM*64 + mf*16 + gid;
        #pragma unroll
        for (int nf = 0; nf < 4; nf++) {
            int col = bx*128 + warpN*32 + nf*8 + tig*2;
            float v0 = c[mf][nf][0], v1 = c[mf][nf][1];
            float v2 = c[mf][nf][2], v3 = c[mf][nf][3];
            if (cvtOut) {
                v0 = __uint_as_float(f2tf32(v0));
                v1 = __uint_as_float(f2tf32(v1));
                v2 = __uint_as_float(f2tf32(v2));
                v3 = __uint_as_float(f2tf32(v3));
            }
            *(float2*)&C[(size_t)row0 * N + col]     = make_float2(v0, v1);
            *(float2*)&C[(size_t)(row0+8) * N + col] = make_float2(v2, v3);
        }
    }
}

// ---------------------------------------------------------------------------
// RoPE for Q and K in one launch; outputs rounded to tf32 (consumed by MMA).
// head-slot hs: 0..31 -> Q head hs; 32..39 -> K head hs-32.
// ---------------------------------------------------------------------------
__global__ void rope_all_kernel(float* __restrict__ Qm,
                                float* __restrict__ Km,
                                const float* __restrict__ fc,
                                const float* __restrict__ fs) {
    int idx = blockIdx.x * blockDim.x + threadIdx.x;
    int total = S * 40 * (HD/2);
    if (idx >= total) return;
    int i  = idx & 63;
    int hs = (idx >> 6) % 40;
    int s  = idx / (64 * 40);
    float c  = fc[s*64 + i];
    float sn = fs[s*64 + i];
    float* p;
    if (hs < 32) p = Qm + (size_t)s * NQ  + hs * HD + 2*i;
    else         p = Km + (size_t)s * NKV + (hs-32) * HD + 2*i;
    float t0 = p[0], t1 = p[1];
    p[0] = __uint_as_float(f2tf32(t0*c - t1*sn));
    p[1] = __uint_as_float(f2tf32(t0*sn + t1*c));
}

// ---------------------------------------------------------------------------
// Flash attention on tf32 MMA. BQ=128, BKV=64. 256 threads = 8 warps;
// warp w owns q-rows w*16..w*16+15 (all 128 dims). Causal, GQA (4 q per kv).
// K/V pre-rounded to tf32 -> cp.async double-buffered byte copies.
// Dynamic smem: Ks[2][64][136] + Vs[2][64][136] + Ps[128][72] = 176128 B.
// ---------------------------------------------------------------------------
#define KP 136
#define PP 72
#define KVT (64*KP)          // floats per K/V buffer
#define FLASH_SMEM ((4*KVT + 128*PP) * 4)

__global__ __launch_bounds__(256)
void flash_mma(const float* __restrict__ Q,
               const float* __restrict__ K,
               const float* __restrict__ V,
               float* __restrict__ O) {
    extern __shared__ float sm[];
    float* Ks = sm;                  // [2][64][KP]
    float* Vs = sm + 2*KVT;         // [2][64][KP]
    float* Ps = sm + 4*KVT;         // [128][PP]

    const int qb  = gridDim.x - 1 - blockIdx.x;   // heavy blocks first
    const int h   = blockIdx.y;
    const int kh  = h >> 2;
    const int tid = threadIdx.x;
    const int lane = tid & 31;
    const int wid  = tid >> 5;
    const int gid  = lane >> 2;
    const int tig  = lane & 3;
    const int m0   = wid * 16;
    const float scale = 0.08838834764831845f;

    const uint32_t smemBase = (uint32_t)__cvta_generic_to_shared(sm);

    // ---- Stage Q tile through Ks buffers, then load Q fragments to regs ----
    #pragma unroll
    for (int i = 0; i < 16; i++) {
        int e = tid + i*256;            // 4096 float4 chunks (128 rows x 32)
        int row = e >> 5;
        int c4  = (e & 31) << 2;
        *(float4*)&Ks[(row>>6)*KVT + (row&63)*KP + c4] =
            *(const float4*)&Q[(size_t)(qb*128 + row)*NQ + h*HD + c4];
    }
    __syncthreads();

    unsigned qf[16][4];
    {
        int r0 = m0 + gid;
        int r1 = r0 + 8;
        const float* q0 = &Ks[(r0>>6)*KVT + (r0&63)*KP];
        const float* q1 = &Ks[(r1>>6)*KVT + (r1&63)*KP];
        #pragma unroll
        for (int ks = 0; ks < 16; ks++) {
            int k0 = ks*8;
            qf[ks][0] = __float_as_uint(q0[k0+tig]);
            qf[ks][1] = __float_as_uint(q1[k0+tig]);
            qf[ks][2] = __float_as_uint(q0[k0+tig+4]);
            qf[ks][3] = __float_as_uint(q1[k0+tig+4]);
        }
    }
    __syncthreads();

    float of[16][4];
    #pragma unroll
    for (int n = 0; n < 16; n++)
        #pragma unroll
        for (int r = 0; r < 4; r++) of[n][r] = 0.f;
    float mrow0 = -INFINITY, mrow1 = -INFINITY;
    float lrow0 = 0.f, lrow1 = 0.f;

    const int nkv = 2*qb + 2;

    // async copy of one KV tile (16B chunks; K/V already tf32-rounded)
    auto issue_tile = [&](int kb) {
        int buf = kb & 1;
        int kv0 = kb * 64;
        #pragma unroll
        for (int j = 0; j < 8; j++) {
            int e = tid + j*256;        // 2048 chunks: 64 rows x 32 float4
            int row = e >> 5;
            int c4  = (e & 31) << 2;
            uint32_t dK = smemBase + (buf*KVT + row*KP + c4) * 4;
            uint32_t dV = smemBase + ((2+buf)*KVT + row*KP + c4) * 4;
            cp16(dK, &K[(size_t)(kv0+row)*NKV + kh*HD + c4]);
            cp16(dV, &V[(size_t)(kv0+row)*NKV + kh*HD + c4]);
        }
    };

    issue_tile(0); cp_commit();
    issue_tile(1); cp_commit();       // nkv >= 2 always

    const int grow0 = qb*128 + m0 + gid;
    const int grow1 = grow0 + 8;

    for (int kb = 0; kb < nkv; kb++) {
        const int buf = kb & 1;
        const int kv0 = kb * 64;
        cp_wait<1>();
        __syncthreads();

        // ---- S = Q K^T (per warp: 16 x 64) ----
        float c[8][4];
        #pragma unroll
        for (int nf = 0; nf < 8; nf++)
            #pragma unroll
            for (int r = 0; r < 4; r++) c[nf][r] = 0.f;

        const float* Kb = &Ks[buf*KVT];
        #pragma unroll
        for (int ks = 0; ks < 16; ks++) {
            int k0 = ks*8;
            #pragma unroll
            for (int nf = 0; nf < 8; nf++) {
                unsigned b0 = __float_as_uint(Kb[(nf*8+gid)*KP + k0+tig]);
                unsigned b1 = __float_as_uint(Kb[(nf*8+gid)*KP + k0+tig+4]);
                mma_tf32(c[nf], qf[ks], b0, b1);
            }
        }

        // ---- scale + causal mask ----
        const bool needmask = (kb >= 2*qb);   // only last two kv blocks overlap diag
        #pragma unroll
        for (int nf = 0; nf < 8; nf++) {
            int gc = kv0 + nf*8 + 2*tig;
            c[nf][0] *= scale; c[nf][1] *= scale;
            c[nf][2] *= scale; c[nf][3] *= scale;
            if (needmask) {
                if (gc   > grow0) c[nf][0] = -INFINITY;
                if (gc+1 > grow0) c[nf][1] = -INFINITY;
                if (gc   > grow1) c[nf][2] = -INFINITY;
                if (gc+1 > grow1) c[nf][3] = -INFINITY;
            }
        }

        // ---- online softmax ----
        float mx0 = -INFINITY, mx1 = -INFINITY;
        #pragma unroll
        for (int nf = 0; nf < 8; nf++) {
            mx0 = fmaxf(mx0, fmaxf(c[nf][0], c[nf][1]));
            mx1 = fmaxf(mx1, fmaxf(c[nf][2], c[nf][3]));
        }
        mx0 = fmaxf(mx0, __shfl_xor_sync(0xffffffffu, mx0, 1));
        mx0 = fmaxf(mx0, __shfl_xor_sync(0xffffffffu, mx0, 2));
        mx1 = fmaxf(mx1, __shfl_xor_sync(0xffffffffu, mx1, 1));
        mx1 = fmaxf(mx1, __shfl_xor_sync(0xffffffffu, mx1, 2));

        float mn0 = fmaxf(mrow0, mx0);
        float mn1 = fmaxf(mrow1, mx1);
        float a0 = __expf(mrow0 - mn0);
        float a1 = __expf(mrow1 - mn1);
        mrow0 = mn0; mrow1 = mn1;

        float s0 = 0.f, s1 = 0.f;
        #pragma unroll
        for (int nf = 0; nf < 8; nf++) {
            c[nf][0] = __expf(c[nf][0] - mn0);
            c[nf][1] = __expf(c[nf][1] - mn0);
            c[nf][2] = __expf(c[nf][2] - mn1);
            c[nf][3] = __expf(c[nf][3] - mn1);
            s0 += c[nf][0] + c[nf][1];
            s1 += c[nf][2] + c[nf][3];
        }
        s0 += __shfl_xor_sync(0xffffffffu, s0, 1);
        s0 += __shfl_xor_sync(0xffffffffu, s0, 2);
        s1 += __shfl_xor_sync(0xffffffffu, s1, 1);
        s1 += __shfl_xor_sync(0xffffffffu, s1, 2);
        lrow0 = lrow0*a0 + s0;
        lrow1 = lrow1*a1 + s1;

        #pragma unroll
        for (int nf = 0; nf < 16; nf++) {
            of[nf][0] *= a0; of[nf][1] *= a0;
            of[nf][2] *= a1; of[nf][3] *= a1;
        }

        // ---- P -> smem (tf32) ----
        {
            float* pr0 = &Ps[(m0+gid)*PP + 2*tig];
            float* pr1 = &Ps[(m0+gid+8)*PP + 2*tig];
            #pragma unroll
            for (int nf = 0; nf < 8; nf++) {
                pr0[nf*8]   = __uint_as_float(f2tf32(c[nf][0]));
                pr0[nf*8+1] = __uint_as_float(f2tf32(c[nf][1]));
                pr1[nf*8]   = __uint_as_float(f2tf32(c[nf][2]));
                pr1[nf*8+1] = __uint_as_float(f2tf32(c[nf][3]));
            }
        }
        __syncwarp();

        // ---- O += P V (per warp: 16 x 128) ----
        const float* Vb = &Vs[buf*KVT];
        #pragma unroll
        for (int ks = 0; ks < 8; ks++) {
            int k0 = ks*8;
            unsigned a[4];
            a[0] = __float_as_uint(Ps[(m0+gid)*PP   + k0+tig]);
            a[1] = __float_as_uint(Ps[(m0+gid+8)*PP + k0+tig]);
            a[2] = __float_as_uint(Ps[(m0+gid)*PP   + k0+tig+4]);
            a[3] = __float_as_uint(Ps[(m0+gid+8)*PP + k0+tig+4]);
            #pragma unroll
            for (int nf = 0; nf < 16; nf++) {
                unsigned b0 = __float_as_uint(Vb[(k0+tig)*KP   + nf*8+gid]);
                unsigned b1 = __float_as_uint(Vb[(k0+tig+4)*KP + nf*8+gid]);
                mma_tf32(of[nf], a, b0, b1);
            }
        }

        __syncthreads();
        if (kb + 2 < nkv) issue_tile(kb + 2);
        cp_commit();
    }

    // ---- epilogue: O /= l ----
    float inv0 = 1.f / lrow0;
    float inv1 = 1.f / lrow1;
    #pragma unroll
    for (int nf = 0; nf < 16; nf++) {
        int col = h*HD + nf*8 + 2*tig;
        *(float2*)&O[(size_t)grow0 * NQ + col] =
            make_float2(of[nf][0]*inv0, of[nf][1]*inv0);
        *(float2*)&O[(size_t)grow1 * NQ + col] =
            make_float2(of[nf][2]*inv1, of[nf][3]*inv1);
    }
}

// ---------------------------------------------------------------------------
// Launch
// ---------------------------------------------------------------------------
extern "C" void kernel_launch(void* const* d_in, const int* in_sizes, int n_in,
                              void* d_out, int out_size) {
    const float* x  = (const float*)d_in[0];
    const float* fc = (const float*)d_in[1];
    const float* fs = (const float*)d_in[2];
    const float* wq = (const float*)d_in[3];
    const float* wk = (const float*)d_in[4];
    const float* wv = (const float*)d_in[5];
    const float* wo = (const float*)d_in[6];
    float* out = (float*)d_out;

    float *Q, *K, *V, *ATT;
    cudaGetSymbolAddress((void**)&Q,   g_Q);
    cudaGetSymbolAddress((void**)&K,   g_K);
    cudaGetSymbolAddress((void**)&V,   g_V);
    cudaGetSymbolAddress((void**)&ATT, g_attn);

    cudaFuncSetAttribute(flash_mma,
        cudaFuncAttributeMaxDynamicSharedMemorySize, FLASH_SMEM);

    // QKV projections (V output rounded to tf32 for flash's cp.async path)
    gemm_tf32<<<dim3(NQ/128,  S/128), 256>>>(S, NQ,  Dm, x, wq, Q, 0);
    gemm_tf32<<<dim3(NKV/128, S/128), 256>>>(S, NKV, Dm, x, wk, K, 0);
    gemm_tf32<<<dim3(NKV/128, S/128), 256>>>(S, NKV, Dm, x, wv, V, 1);

    // RoPE on Q and K (one launch; outputs tf32-rounded)
    {
        int total = S * 40 * (HD/2);
        rope_all_kernel<<<(total + 255)/256, 256>>>(Q, K, fc, fs);
    }

    // Causal GQA flash attention (tensor cores)
    flash_mma<<<dim3(S/128, HQ), 256, FLASH_SMEM>>>(Q, K, V, ATT);

    // Output projection
    gemm_tf32<<<dim3(Dm/128, S/128), 256>>>(S, Dm, NQ, ATT, wo, out, 0);
}

// round 4
// speedup vs baseline: 7.6777x; 1.2050x over previous
#include <cuda_runtime.h>
#include <math.h>
#include <stdint.h>

// Problem dims
#define S   2048
#define Dm  4096
#define HQ  32
#define HK  8
#define HD  128
#define NQ  (HQ*HD)   // 4096
#define NKV (HK*HD)   // 1024

// Scratch (device globals; no allocations allowed)
__device__ float g_Q[S*NQ];
__device__ float g_K[S*NKV];
__device__ float g_V[S*NKV];
__device__ float g_attn[S*NQ];
// tf32-pre-rounded copies of GEMM inputs
__device__ float g_X [S*Dm];
__device__ float g_Wq[Dm*NQ];
__device__ float g_Wk[Dm*NKV];
__device__ float g_Wv[Dm*NKV];
__device__ float g_Wo[NQ*Dm];

__device__ __forceinline__ unsigned f2tf32(float f) {
    unsigned r;
    asm("cvt.rna.tf32.f32 %0, %1;" : "=r"(r) : "f"(f));
    return r;
}

__device__ __forceinline__ void mma_tf32(float c[4], const unsigned a[4],
                                         unsigned b0, unsigned b1) {
    asm volatile(
        "mma.sync.aligned.m16n8k8.row.col.f32.tf32.tf32.f32 "
        "{%0,%1,%2,%3}, {%4,%5,%6,%7}, {%8,%9}, {%0,%1,%2,%3};"
        : "+f"(c[0]), "+f"(c[1]), "+f"(c[2]), "+f"(c[3])
        : "r"(a[0]), "r"(a[1]), "r"(a[2]), "r"(a[3]), "r"(b0), "r"(b1));
}

__device__ __forceinline__ void cp16(uint32_t dst, const void* src) {
    asm volatile("cp.async.cg.shared.global [%0], [%1], 16;\n" :: "r"(dst), "l"(src));
}
__device__ __forceinline__ void cp_commit() {
    asm volatile("cp.async.commit_group;\n");
}
template<int N> __device__ __forceinline__ void cp_wait() {
    asm volatile("cp.async.wait_group %0;\n" :: "n"(N));
}

// ---------------------------------------------------------------------------
// Prep: round fp32 array to tf32 (vectorized). n must be divisible by 4.
// ---------------------------------------------------------------------------
__global__ void round_tf32_kernel(const float* __restrict__ src,
                                  float* __restrict__ dst, int n4) {
    int i = blockIdx.x * blockDim.x + threadIdx.x;
    if (i >= n4) return;
    float4 v = ((const float4*)src)[i];
    v.x = __uint_as_float(f2tf32(v.x));
    v.y = __uint_as_float(f2tf32(v.y));
    v.z = __uint_as_float(f2tf32(v.z));
    v.w = __uint_as_float(f2tf32(v.w));
    ((float4*)dst)[i] = v;
}

// ---------------------------------------------------------------------------
// tf32 tensor-core GEMM, cp.async 4-stage pipeline.
// C[M,N] = A[M,K] @ B[K,N], row-major. Inputs MUST be tf32-pre-rounded.
// 128x128 CTA tile, BK=16. 8 warps, each 64(M)x32(N).
// Requires M%128==0, N%128==0, K%16==0.
// ---------------------------------------------------------------------------
#define APITCH 20    // floats per A smem row (128 rows x 16 cols)
#define BPITCH 132   // floats per B smem row (16 rows x 128 cols)
#define ASZ (128*APITCH)   // 2560 floats
#define BSZ (16*BPITCH)    // 2112 floats
#define STAGES 4
#define GEMM_SMEM (STAGES*(ASZ+BSZ)*4)   // 74752 B

__global__ __launch_bounds__(256)
void gemm_tf32(int M, int N, int K,
               const float* __restrict__ A,
               const float* __restrict__ B,
               float* __restrict__ C, int cvtOut) {
    extern __shared__ float sm[];
    float* As = sm;                       // [STAGES][128][APITCH]
    float* Bs = sm + STAGES*ASZ;          // [STAGES][16][BPITCH]
    const uint32_t smemBase = (uint32_t)__cvta_generic_to_shared(sm);

    const int tid  = threadIdx.x;
    const int lane = tid & 31;
    const int wid  = tid >> 5;
    const int gid  = lane >> 2;
    const int tig  = lane & 3;
    const int warpM = wid >> 2;   // 0..1
    const int warpN = wid & 3;    // 0..3
    const int m0 = warpM*64;
    const int n0 = warpN*32;

    const int bx = blockIdx.x;
    const int by = blockIdx.y;

    // load mapping: 1024 16B chunks per tile; thread does 4 (2 A + 2 B)
    // A chunks e=0..511: row=e>>2, c4=(e&3)*4
    // B chunks e=0..511: row=e>>5, col4=(e&31)*4
    const int aRow0 = tid >> 1;            // chunks 2*tid, 2*tid+1 -> same pattern:
    // use explicit per-j mapping below.

    auto issue_tile = [&](int t) {
        const int slot = t % STAGES;
        #pragma unroll
        for (int j = 0; j < 2; j++) {
            int e = tid + j*256;           // A chunk id
            int row = e >> 2;
            int c4  = (e & 3) << 2;
            uint32_t dst = smemBase + (slot*ASZ + row*APITCH + c4)*4;
            cp16(dst, &A[(size_t)(by*128 + row)*K + t*16 + c4]);
        }
        #pragma unroll
        for (int j = 0; j < 2; j++) {
            int e = tid + j*256;           // B chunk id
            int row = e >> 5;
            int col4 = (e & 31) << 2;
            uint32_t dst = smemBase + (STAGES*ASZ*0 + 0)*4; (void)dst;
            uint32_t d = smemBase + (STAGES*ASZ + slot*BSZ + row*BPITCH + col4)*4;
            cp16(d, &B[(size_t)(t*16 + row)*N + bx*128 + col4]);
        }
    };

    float c[4][4][4];
    #pragma unroll
    for (int i = 0; i < 4; i++)
        #pragma unroll
        for (int j = 0; j < 4; j++)
            #pragma unroll
            for (int r = 0; r < 4; r++) c[i][j][r] = 0.f;

    const int nt = K / 16;

    // prologue: fill STAGES-1 stages
    #pragma unroll
    for (int t = 0; t < STAGES-1; t++) {
        if (t < nt) issue_tile(t);
        cp_commit();
    }

    for (int t = 0; t < nt; t++) {
        cp_wait<STAGES-2>();
        __syncthreads();

        if (t + STAGES-1 < nt) issue_tile(t + STAGES-1);
        cp_commit();

        const int slot = t % STAGES;
        const float* Asl = As + slot*ASZ;
        const float* Bsl = Bs + slot*BSZ;

        #pragma unroll
        for (int ks = 0; ks < 16; ks += 8) {
            unsigned af[4][4], bf[4][2];
            #pragma unroll
            for (int mf = 0; mf < 4; mf++) {
                int r0 = m0 + mf*16 + gid;
                af[mf][0] = __float_as_uint(Asl[(r0  )*APITCH + ks + tig]);
                af[mf][1] = __float_as_uint(Asl[(r0+8)*APITCH + ks + tig]);
                af[mf][2] = __float_as_uint(Asl[(r0  )*APITCH + ks + tig + 4]);
                af[mf][3] = __float_as_uint(Asl[(r0+8)*APITCH + ks + tig + 4]);
            }
            #pragma unroll
            for (int nf = 0; nf < 4; nf++) {
                int nn = n0 + nf*8 + gid;
                bf[nf][0] = __float_as_uint(Bsl[(ks+tig  )*BPITCH + nn]);
                bf[nf][1] = __float_as_uint(Bsl[(ks+tig+4)*BPITCH + nn]);
            }
            #pragma unroll
            for (int mf = 0; mf < 4; mf++)
                #pragma unroll
                for (int nf = 0; nf < 4; nf++)
                    mma_tf32(c[mf][nf], af[mf], bf[nf][0], bf[nf][1]);
        }
    }

    // epilogue
    #pragma unroll
    for (int mf = 0; mf < 4; mf++) {
        int row0 = by*128 + m0 + mf*16 + gid;
        #pragma unroll
        for (int nf = 0; nf < 4; nf++) {
            int col = bx*128 + n0 + nf*8 + tig*2;
            float v0 = c[mf][nf][0], v1 = c[mf][nf][1];
            float v2 = c[mf][nf][2], v3 = c[mf][nf][3];
            if (cvtOut) {
                v0 = __uint_as_float(f2tf32(v0));
                v1 = __uint_as_float(f2tf32(v1));
                v2 = __uint_as_float(f2tf32(v2));
                v3 = __uint_as_float(f2tf32(v3));
            }
            *(float2*)&C[(size_t)row0 * N + col]     = make_float2(v0, v1);
            *(float2*)&C[(size_t)(row0+8) * N + col] = make_float2(v2, v3);
        }
    }
}

// ---------------------------------------------------------------------------
// RoPE for Q and K in one launch; outputs rounded to tf32.
// ---------------------------------------------------------------------------
__global__ void rope_all_kernel(float* __restrict__ Qm,
                                float* __restrict__ Km,
                                const float* __restrict__ fc,
                                const float* __restrict__ fs) {
    int idx = blockIdx.x * blockDim.x + threadIdx.x;
    int total = S * 40 * (HD/2);
    if (idx >= total) return;
    int i  = idx & 63;
    int hs = (idx >> 6) % 40;
    int s  = idx / (64 * 40);
    float c  = fc[s*64 + i];
    float sn = fs[s*64 + i];
    float* p;
    if (hs < 32) p = Qm + (size_t)s * NQ  + hs * HD + 2*i;
    else         p = Km + (size_t)s * NKV + (hs-32) * HD + 2*i;
    float t0 = p[0], t1 = p[1];
    p[0] = __uint_as_float(f2tf32(t0*c - t1*sn));
    p[1] = __uint_as_float(f2tf32(t0*sn + t1*c));
}

// ---------------------------------------------------------------------------
// Flash attention on tf32 MMA. BQ=128, BKV=64. 8 warps, warp w owns q-rows
// w*16..w*16+15. Causal, GQA. K/V tf32-rounded -> cp.async double-buffered.
// ---------------------------------------------------------------------------
#define KP 136
#define PP 72
#define KVT (64*KP)
#define FLASH_SMEM ((4*KVT + 128*PP) * 4)

__global__ __launch_bounds__(256)
void flash_mma(const float* __restrict__ Q,
               const float* __restrict__ K,
               const float* __restrict__ V,
               float* __restrict__ O) {
    extern __shared__ float sm[];
    float* Ks = sm;                  // [2][64][KP]
    float* Vs = sm + 2*KVT;         // [2][64][KP]
    float* Ps = sm + 4*KVT;         // [128][PP]

    const int qb  = gridDim.x - 1 - blockIdx.x;   // heavy blocks first
    const int h   = blockIdx.y;
    const int kh  = h >> 2;
    const int tid = threadIdx.x;
    const int lane = tid & 31;
    const int wid  = tid >> 5;
    const int gid  = lane >> 2;
    const int tig  = lane & 3;
    const int m0   = wid * 16;
    const float scale = 0.08838834764831845f;

    const uint32_t smemBase = (uint32_t)__cvta_generic_to_shared(sm);

    // Stage Q tile through Ks buffers, then load fragments to regs
    #pragma unroll
    for (int i = 0; i < 16; i++) {
        int e = tid + i*256;
        int row = e >> 5;
        int c4  = (e & 31) << 2;
        *(float4*)&Ks[(row>>6)*KVT + (row&63)*KP + c4] =
            *(const float4*)&Q[(size_t)(qb*128 + row)*NQ + h*HD + c4];
    }
    __syncthreads();

    unsigned qf[16][4];
    {
        int r0 = m0 + gid;
        int r1 = r0 + 8;
        const float* q0 = &Ks[(r0>>6)*KVT + (r0&63)*KP];
        const float* q1 = &Ks[(r1>>6)*KVT + (r1&63)*KP];
        #pragma unroll
        for (int ks = 0; ks < 16; ks++) {
            int k0 = ks*8;
            qf[ks][0] = __float_as_uint(q0[k0+tig]);
            qf[ks][1] = __float_as_uint(q1[k0+tig]);
            qf[ks][2] = __float_as_uint(q0[k0+tig+4]);
            qf[ks][3] = __float_as_uint(q1[k0+tig+4]);
        }
    }
    __syncthreads();

    float of[16][4];
    #pragma unroll
    for (int n = 0; n < 16; n++)
        #pragma unroll
        for (int r = 0; r < 4; r++) of[n][r] = 0.f;
    float mrow0 = -INFINITY, mrow1 = -INFINITY;
    float lrow0 = 0.f, lrow1 = 0.f;

    const int nkv = 2*qb + 2;

    auto issue_tile = [&](int kb) {
        int buf = kb & 1;
        int kv0 = kb * 64;
        #pragma unroll
        for (int j = 0; j < 8; j++) {
            int e = tid + j*256;
            int row = e >> 5;
            int c4  = (e & 31) << 2;
            uint32_t dK = smemBase + (buf*KVT + row*KP + c4) * 4;
            uint32_t dV = smemBase + ((2+buf)*KVT + row*KP + c4) * 4;
            cp16(dK, &K[(size_t)(kv0+row)*NKV + kh*HD + c4]);
            cp16(dV, &V[(size_t)(kv0+row)*NKV + kh*HD + c4]);
        }
    };

    issue_tile(0); cp_commit();
    issue_tile(1); cp_commit();

    const int grow0 = qb*128 + m0 + gid;
    const int grow1 = grow0 + 8;

    for (int kb = 0; kb < nkv; kb++) {
        const int buf = kb & 1;
        const int kv0 = kb * 64;
        cp_wait<1>();
        __syncthreads();

        // S = Q K^T
        float c[8][4];
        #pragma unroll
        for (int nf = 0; nf < 8; nf++)
            #pragma unroll
            for (int r = 0; r < 4; r++) c[nf][r] = 0.f;

        const float* Kb = &Ks[buf*KVT];
        #pragma unroll
        for (int ks = 0; ks < 16; ks++) {
            int k0 = ks*8;
            #pragma unroll
            for (int nf = 0; nf < 8; nf++) {
                unsigned b0 = __float_as_uint(Kb[(nf*8+gid)*KP + k0+tig]);
                unsigned b1 = __float_as_uint(Kb[(nf*8+gid)*KP + k0+tig+4]);
                mma_tf32(c[nf], qf[ks], b0, b1);
            }
        }

        const bool needmask = (kb >= 2*qb);
        #pragma unroll
        for (int nf = 0; nf < 8; nf++) {
            int gc = kv0 + nf*8 + 2*tig;
            c[nf][0] *= scale; c[nf][1] *= scale;
            c[nf][2] *= scale; c[nf][3] *= scale;
            if (needmask) {
                if (gc   > grow0) c[nf][0] = -INFINITY;
                if (gc+1 > grow0) c[nf][1] = -INFINITY;
                if (gc   > grow1) c[nf][2] = -INFINITY;
                if (gc+1 > grow1) c[nf][3] = -INFINITY;
            }
        }

        // online softmax
        float mx0 = -INFINITY, mx1 = -INFINITY;
        #pragma unroll
        for (int nf = 0; nf < 8; nf++) {
            mx0 = fmaxf(mx0, fmaxf(c[nf][0], c[nf][1]));
            mx1 = fmaxf(mx1, fmaxf(c[nf][2], c[nf][3]));
        }
        mx0 = fmaxf(mx0, __shfl_xor_sync(0xffffffffu, mx0, 1));
        mx0 = fmaxf(mx0, __shfl_xor_sync(0xffffffffu, mx0, 2));
        mx1 = fmaxf(mx1, __shfl_xor_sync(0xffffffffu, mx1, 1));
        mx1 = fmaxf(mx1, __shfl_xor_sync(0xffffffffu, mx1, 2));

        float mn0 = fmaxf(mrow0, mx0);
        float mn1 = fmaxf(mrow1, mx1);
        float a0 = __expf(mrow0 - mn0);
        float a1 = __expf(mrow1 - mn1);
        mrow0 = mn0; mrow1 = mn1;

        float s0 = 0.f, s1 = 0.f;
        #pragma unroll
        for (int nf = 0; nf < 8; nf++) {
            c[nf][0] = __expf(c[nf][0] - mn0);
            c[nf][1] = __expf(c[nf][1] - mn0);
            c[nf][2] = __expf(c[nf][2] - mn1);
            c[nf][3] = __expf(c[nf][3] - mn1);
            s0 += c[nf][0] + c[nf][1];
            s1 += c[nf][2] + c[nf][3];
        }
        s0 += __shfl_xor_sync(0xffffffffu, s0, 1);
        s0 += __shfl_xor_sync(0xffffffffu, s0, 2);
        s1 += __shfl_xor_sync(0xffffffffu, s1, 1);
        s1 += __shfl_xor_sync(0xffffffffu, s1, 2);
        lrow0 = lrow0*a0 + s0;
        lrow1 = lrow1*a1 + s1;

        #pragma unroll
        for (int nf = 0; nf < 16; nf++) {
            of[nf][0] *= a0; of[nf][1] *= a0;
            of[nf][2] *= a1; of[nf][3] *= a1;
        }

        // P -> smem (tf32)
        {
            float* pr0 = &Ps[(m0+gid)*PP + 2*tig];
            float* pr1 = &Ps[(m0+gid+8)*PP + 2*tig];
            #pragma unroll
            for (int nf = 0; nf < 8; nf++) {
                pr0[nf*8]   = __uint_as_float(f2tf32(c[nf][0]));
                pr0[nf*8+1] = __uint_as_float(f2tf32(c[nf][1]));
                pr1[nf*8]   = __uint_as_float(f2tf32(c[nf][2]));
                pr1[nf*8+1] = __uint_as_float(f2tf32(c[nf][3]));
            }
        }
        __syncwarp();

        // O += P V
        const float* Vb = &Vs[buf*KVT];
        #pragma unroll
        for (int ks = 0; ks < 8; ks++) {
            int k0 = ks*8;
            unsigned a[4];
            a[0] = __float_as_uint(Ps[(m0+gid)*PP   + k0+tig]);
            a[1] = __float_as_uint(Ps[(m0+gid+8)*PP + k0+tig]);
            a[2] = __float_as_uint(Ps[(m0+gid)*PP   + k0+tig+4]);
            a[3] = __float_as_uint(Ps[(m0+gid+8)*PP + k0+tig+4]);
            #pragma unroll
            for (int nf = 0; nf < 16; nf++) {
                unsigned b0 = __float_as_uint(Vb[(k0+tig)*KP   + nf*8+gid]);
                unsigned b1 = __float_as_uint(Vb[(k0+tig+4)*KP + nf*8+gid]);
                mma_tf32(of[nf], a, b0, b1);
            }
        }

        __syncthreads();
        if (kb + 2 < nkv) issue_tile(kb + 2);
        cp_commit();
    }

    // epilogue: O /= l, rounded to tf32 (consumed by O-proj GEMM)
    float inv0 = 1.f / lrow0;
    float inv1 = 1.f / lrow1;
    #pragma unroll
    for (int nf = 0; nf < 16; nf++) {
        int col = h*HD + nf*8 + 2*tig;
        *(float2*)&O[(size_t)grow0 * NQ + col] = make_float2(
            __uint_as_float(f2tf32(of[nf][0]*inv0)),
            __uint_as_float(f2tf32(of[nf][1]*inv0)));
        *(float2*)&O[(size_t)grow1 * NQ + col] = make_float2(
            __uint_as_float(f2tf32(of[nf][2]*inv1)),
            __uint_as_float(f2tf32(of[nf][3]*inv1)));
    }
}

// ---------------------------------------------------------------------------
// Launch
// ---------------------------------------------------------------------------
extern "C" void kernel_launch(void* const* d_in, const int* in_sizes, int n_in,
                              void* d_out, int out_size) {
    const float* x  = (const float*)d_in[0];
    const float* fc = (const float*)d_in[1];
    const float* fs = (const float*)d_in[2];
    const float* wq = (const float*)d_in[3];
    const float* wk = (const float*)d_in[4];
    const float* wv = (const float*)d_in[5];
    const float* wo = (const float*)d_in[6];
    float* out = (float*)d_out;

    float *Q, *K, *V, *ATT, *Xt, *Wqt, *Wkt, *Wvt, *Wot;
    cudaGetSymbolAddress((void**)&Q,   g_Q);
    cudaGetSymbolAddress((void**)&K,   g_K);
    cudaGetSymbolAddress((void**)&V,   g_V);
    cudaGetSymbolAddress((void**)&ATT, g_attn);
    cudaGetSymbolAddress((void**)&Xt,  g_X);
    cudaGetSymbolAddress((void**)&Wqt, g_Wq);
    cudaGetSymbolAddress((void**)&Wkt, g_Wk);
    cudaGetSymbolAddress((void**)&Wvt, g_Wv);
    cudaGetSymbolAddress((void**)&Wot, g_Wo);

    cudaFuncSetAttribute(flash_mma,
        cudaFuncAttributeMaxDynamicSharedMemorySize, FLASH_SMEM);
    cudaFuncSetAttribute(gemm_tf32,
        cudaFuncAttributeMaxDynamicSharedMemorySize, GEMM_SMEM);

    // Prep: tf32-round all GEMM inputs
    {
        int n4;
        n4 = S*Dm/4;    round_tf32_kernel<<<(n4+255)/256, 256>>>(x,  Xt,  n4);
        n4 = Dm*NQ/4;   round_tf32_kernel<<<(n4+255)/256, 256>>>(wq, Wqt, n4);
        n4 = Dm*NKV/4;  round_tf32_kernel<<<(n4+255)/256, 256>>>(wk, Wkt, n4);
        n4 = Dm*NKV/4;  round_tf32_kernel<<<(n4+255)/256, 256>>>(wv, Wvt, n4);
        n4 = NQ*Dm/4;   round_tf32_kernel<<<(n4+255)/256, 256>>>(wo, Wot, n4);
    }

    // QKV projections (V output rounded to tf32 for flash)
    gemm_tf32<<<dim3(NQ/128,  S/128), 256, GEMM_SMEM>>>(S, NQ,  Dm, Xt, Wqt, Q, 0);
    gemm_tf32<<<dim3(NKV/128, S/128), 256, GEMM_SMEM>>>(S, NKV, Dm, Xt, Wkt, K, 0);
    gemm_tf32<<<dim3(NKV/128, S/128), 256, GEMM_SMEM>>>(S, NKV, Dm, Xt, Wvt, V, 1);

    // RoPE on Q and K (rounds outputs to tf32)
    {
        int total = S * 40 * (HD/2);
        rope_all_kernel<<<(total + 255)/256, 256>>>(Q, K, fc, fs);
    }

    // Causal GQA flash attention (writes tf32-rounded ATT)
    flash_mma<<<dim3(S/128, HQ), 256, FLASH_SMEM>>>(Q, K, V, ATT);

    // Output projection
    gemm_tf32<<<dim3(Dm/128, S/128), 256, GEMM_SMEM>>>(S, Dm, NQ, ATT, Wot, out, 0);
}

// round 7
// speedup vs baseline: 12.5914x; 1.6400x over previous
#include <cuda_runtime.h>
#include <cuda_fp16.h>
#include <math.h>
#include <stdint.h>

// Problem dims
#define S   2048
#define Dm  4096
#define HQ  32
#define HK  8
#define HD  128
#define NQ  (HQ*HD)   // 4096
#define NKV (HK*HD)   // 1024

// Scratch (device globals; no allocations allowed). All fp16.
__device__ __half g_Q[S*NQ];
__device__ __half g_K[S*NKV];
__device__ __half g_V[S*NKV];
__device__ __half g_attn[S*NQ];
__device__ __half g_X [S*Dm];        // x rounded to half, [S][Dm]
__device__ __half g_Wq[Dm*NQ];       // transposed: [NQ][Dm]
__device__ __half g_Wk[Dm*NKV];      // [NKV][Dm]
__device__ __half g_Wv[Dm*NKV];      // [NKV][Dm]
__device__ __half g_Wo[NQ*Dm];       // [Dm][NQ]

// ---------------------------------------------------------------------------
// helpers
// ---------------------------------------------------------------------------
__device__ __forceinline__ void mma_f16(float c[4], const unsigned a[4],
                                        unsigned b0, unsigned b1) {
    asm volatile(
        "mma.sync.aligned.m16n8k16.row.col.f32.f16.f16.f32 "
        "{%0,%1,%2,%3}, {%4,%5,%6,%7}, {%8,%9}, {%0,%1,%2,%3};"
        : "+f"(c[0]), "+f"(c[1]), "+f"(c[2]), "+f"(c[3])
        : "r"(a[0]), "r"(a[1]), "r"(a[2]), "r"(a[3]), "r"(b0), "r"(b1));
}

__device__ __forceinline__ void cp16(uint32_t dst, const void* src) {
    asm volatile("cp.async.cg.shared.global [%0], [%1], 16;\n" :: "r"(dst), "l"(src));
}
__device__ __forceinline__ void cp_commit() {
    asm volatile("cp.async.commit_group;\n");
}
template<int N> __device__ __forceinline__ void cp_wait() {
    asm volatile("cp.async.wait_group %0;\n" :: "n"(N));
}

__device__ __forceinline__ unsigned ldh(const __half* p) {   // 4B-aligned half2
    return *(const unsigned*)p;
}
__device__ __forceinline__ unsigned pack_h2(const __half* p0, const __half* p1) {
    unsigned short h0 = *(const unsigned short*)p0;
    unsigned short h1 = *(const unsigned short*)p1;
    return (unsigned)h0 | ((unsigned)h1 << 16);
}

// ---------------------------------------------------------------------------
// Prep: fp32 -> fp16 (vectorized). n4 = n/4.
// ---------------------------------------------------------------------------
__global__ void f2h_kernel(const float* __restrict__ src,
                           __half* __restrict__ dst, int n4) {
    int i = blockIdx.x * blockDim.x + threadIdx.x;
    if (i >= n4) return;
    float4 v = ((const float4*)src)[i];
    *(__half2*)&dst[4*i]     = __floats2half2_rn(v.x, v.y);
    *(__half2*)&dst[4*i + 2] = __floats2half2_rn(v.z, v.w);
}

// ---------------------------------------------------------------------------
// Prep: transpose fp32 [R][C] -> fp16 [C][R]. R,C % 32 == 0.
// ---------------------------------------------------------------------------
__global__ void transpose_f2h_kernel(const float* __restrict__ src,
                                     __half* __restrict__ dst, int R, int C) {
    __shared__ float tile[32][33];
    int c0 = blockIdx.x * 32, r0 = blockIdx.y * 32;
    int x = threadIdx.x, y = threadIdx.y;
    #pragma unroll
    for (int i = y; i < 32; i += 8)
        tile[i][x] = src[(size_t)(r0 + i) * C + c0 + x];
    __syncthreads();
    #pragma unroll
    for (int i = y; i < 32; i += 8)
        dst[(size_t)(c0 + i) * R + r0 + x] = __float2half_rn(tile[x][i]);
}

// ---------------------------------------------------------------------------
// fp16 tensor-core GEMM, cp.async 4-stage pipeline.
// C[M,N] = A[M,K] @ Bt[N,K]^T.  A half [M][K], Bt half [N][K] (both K-major).
// 128x128 CTA tile, BK=32. 8 warps, each 64(M)x32(N). m16n8k16.
// Requires M%128==0, N%128==0, K%32==0, K/32 >= 3.
// outHalf: write C as half; else fp32.
// ---------------------------------------------------------------------------
#define APITCH 40                 // halves per smem row (32 data + 8 pad)
#define ASZ (128*APITCH)          // halves per A (or B) tile = 5120
#define GSTAGES 4
#define STAGE_HALVES (2*ASZ)      // 10240 halves = 20480 B
#define GEMM_SMEM (GSTAGES*STAGE_HALVES*2)   // 81920 B

__global__ __launch_bounds__(256)
void gemm_f16(int M, int N, int K,
              const __half* __restrict__ A,
              const __half* __restrict__ Bt,
              void* __restrict__ Cv, int outHalf) {
    extern __shared__ __half smh[];
    const uint32_t smemBase = (uint32_t)__cvta_generic_to_shared(smh);

    const int tid  = threadIdx.x;
    const int lane = tid & 31;
    const int wid  = tid >> 5;
    const int gid  = lane >> 2;   // 0..7
    const int tig  = lane & 3;    // 0..3
    const int warpM = wid >> 2;   // 0..1
    const int warpN = wid & 3;    // 0..3
    const int m0 = warpM*64;
    const int n0 = warpN*32;

    const int bx = blockIdx.x;    // N tile
    const int by = blockIdx.y;    // M tile

    const __half* Abase = A  + (size_t)(by*128) * K;
    const __half* Bbase = Bt + (size_t)(bx*128) * K;

    // one K-tile (32 cols): A 128 rows x 4 chunks16B, B same -> 1024 chunks
    auto issue_tile = [&](int t) {
        const int slot = t % GSTAGES;
        const uint32_t stA = smemBase + slot*STAGE_HALVES*2;
        const uint32_t stB = stA + ASZ*2;
        const __half* Ag = Abase + t*32;
        const __half* Bg = Bbase + t*32;
        #pragma unroll
        for (int j = 0; j < 2; j++) {
            int e = tid + j*256;            // 0..511
            int row = e >> 2, ch = e & 3;
            cp16(stA + (row*APITCH + ch*8)*2, Ag + (size_t)row*K + ch*8);
        }
        #pragma unroll
        for (int j = 0; j < 2; j++) {
            int e = tid + j*256;
            int row = e >> 2, ch = e & 3;
            cp16(stB + (row*APITCH + ch*8)*2, Bg + (size_t)row*K + ch*8);
        }
    };

    float c[4][4][4];
    #pragma unroll
    for (int i = 0; i < 4; i++)
        #pragma unroll
        for (int j = 0; j < 4; j++)
            #pragma unroll
            for (int r = 0; r < 4; r++) c[i][j][r] = 0.f;

    const int nt = K / 32;

    #pragma unroll
    for (int t = 0; t < GSTAGES-1; t++) {
        if (t < nt) issue_tile(t);
        cp_commit();
    }

    for (int t = 0; t < nt; t++) {
        cp_wait<GSTAGES-2>();
        __syncthreads();

        if (t + GSTAGES-1 < nt) issue_tile(t + GSTAGES-1);
        cp_commit();

        const int slot = t % GSTAGES;
        const __half* Asl = smh + slot*STAGE_HALVES;
        const __half* Bsl = Asl + ASZ;

        #pragma unroll
        for (int ks = 0; ks < 32; ks += 16) {
            unsigned af[4][4], bf[4][2];
            #pragma unroll
            for (int mf = 0; mf < 4; mf++) {
                const __half* r0p = Asl + (m0 + mf*16 + gid)*APITCH + ks + 2*tig;
                const __half* r1p = r0p + 8*APITCH;
                af[mf][0] = ldh(r0p);
                af[mf][1] = ldh(r1p);
                af[mf][2] = ldh(r0p + 8);
                af[mf][3] = ldh(r1p + 8);
            }
            #pragma unroll
            for (int nf = 0; nf < 4; nf++) {
                const __half* bp = Bsl + (n0 + nf*8 + gid)*APITCH + ks + 2*tig;
                bf[nf][0] = ldh(bp);
                bf[nf][1] = ldh(bp + 8);
            }
            #pragma unroll
            for (int mf = 0; mf < 4; mf++)
                #pragma unroll
                for (int nf = 0; nf < 4; nf++)
                    mma_f16(c[mf][nf], af[mf], bf[nf][0], bf[nf][1]);
        }
    }

    // epilogue
    #pragma unroll
    for (int mf = 0; mf < 4; mf++) {
        int row0 = by*128 + m0 + mf*16 + gid;
        #pragma unroll
        for (int nf = 0; nf < 4; nf++) {
            int col = bx*128 + n0 + nf*8 + tig*2;
            if (outHalf) {
                __half* Ch = (__half*)Cv;
                *(__half2*)&Ch[(size_t)row0 * N + col] =
                    __floats2half2_rn(c[mf][nf][0], c[mf][nf][1]);
                *(__half2*)&Ch[(size_t)(row0+8) * N + col] =
                    __floats2half2_rn(c[mf][nf][2], c[mf][nf][3]);
            } else {
                float* Cf = (float*)Cv;
                *(float2*)&Cf[(size_t)row0 * N + col] =
                    make_float2(c[mf][nf][0], c[mf][nf][1]);
                *(float2*)&Cf[(size_t)(row0+8) * N + col] =
                    make_float2(c[mf][nf][2], c[mf][nf][3]);
            }
        }
    }
}

// ---------------------------------------------------------------------------
// RoPE for Q and K (half in/out, fp32 math), one launch.
// ---------------------------------------------------------------------------
__global__ void rope_all_kernel(__half* __restrict__ Qm,
                                __half* __restrict__ Km,
                                const float* __restrict__ fc,
                                const float* __restrict__ fs) {
    int idx = blockIdx.x * blockDim.x + threadIdx.x;
    int total = S * 40 * (HD/2);
    if (idx >= total) return;
    int i  = idx & 63;
    int hs = (idx >> 6) % 40;
    int s  = idx / (64 * 40);
    float c  = fc[s*64 + i];
    float sn = fs[s*64 + i];
    __half* p;
    if (hs < 32) p = Qm + (size_t)s * NQ  + hs * HD + 2*i;
    else         p = Km + (size_t)s * NKV + (hs-32) * HD + 2*i;
    __half2 v = *(__half2*)p;
    float t0 = __low2float(v), t1 = __high2float(v);
    *(__half2*)p = __floats2half2_rn(t0*c - t1*sn, t0*sn + t1*c);
}

// ---------------------------------------------------------------------------
// Flash attention on fp16 MMA. BQ=128, BKV=64. 8 warps, warp w owns q-rows
// w*16..w*16+15. Causal, GQA (4 q heads per kv head).
// ---------------------------------------------------------------------------
#define KP 136                    // halves per K/V smem row
#define PP 72                     // halves per P smem row
#define KVT (64*KP)               // halves per K/V buffer = 8704
#define FLASH_SMEM ((4*KVT + 128*PP) * 2)   // 88064 B

__global__ __launch_bounds__(256)
void flash_f16(const __half* __restrict__ Q,
               const __half* __restrict__ K,
               const __half* __restrict__ V,
               __half* __restrict__ O) {
    extern __shared__ __half smh[];
    __half* Ks = smh;                 // [2][64][KP]
    __half* Vs = smh + 2*KVT;         // [2][64][KP]
    __half* Ps = smh + 4*KVT;         // [128][PP]

    const int qb  = gridDim.x - 1 - blockIdx.x;   // heavy blocks first
    const int h   = blockIdx.y;
    const int kh  = h >> 2;
    const int tid = threadIdx.x;
    const int lane = tid & 31;
    const int wid  = tid >> 5;
    const int gid  = lane >> 2;
    const int tig  = lane & 3;
    const int m0   = wid * 16;
    const float scale = 0.08838834764831845f;

    const uint32_t smemBase = (uint32_t)__cvta_generic_to_shared(smh);

    // Stage Q tile (128 x 128 halves) through Ks area, pitch KP
    #pragma unroll
    for (int i = 0; i < 8; i++) {
        int e = tid + i*256;           // 0..2047 chunks of 8 halves
        int row = e >> 4;
        int ch  = e & 15;
        *(float4*)&Ks[row*KP + ch*8] =
            *(const float4*)&Q[(size_t)(qb*128 + row)*NQ + h*HD + ch*8];
    }
    __syncthreads();

    // Q fragments: 8 k-steps of 16
    unsigned qf[8][4];
    {
        const __half* q0 = Ks + (m0 + gid)*KP;
        const __half* q1 = q0 + 8*KP;
        #pragma unroll
        for (int ks = 0; ks < 8; ks++) {
            int k0 = ks*16 + 2*tig;
            qf[ks][0] = ldh(q0 + k0);
            qf[ks][1] = ldh(q1 + k0);
            qf[ks][2] = ldh(q0 + k0 + 8);
            qf[ks][3] = ldh(q1 + k0 + 8);
        }
    }
    __syncthreads();

    float of[16][4];
    #pragma unroll
    for (int n = 0; n < 16; n++)
        #pragma unroll
        for (int r = 0; r < 4; r++) of[n][r] = 0.f;
    float mrow0 = -INFINITY, mrow1 = -INFINITY;
    float lrow0 = 0.f, lrow1 = 0.f;

    const int nkv = 2*qb + 2;

    auto issue_tile = [&](int kb) {
        int buf = kb & 1;
        int kv0 = kb * 64;
        #pragma unroll
        for (int j = 0; j < 4; j++) {
            int e = tid + j*256;        // 0..1023: 64 rows x 16 chunks
            int row = e >> 4;
            int ch  = e & 15;
            cp16(smemBase + (buf*KVT + row*KP + ch*8)*2,
                 &K[(size_t)(kv0+row)*NKV + kh*HD + ch*8]);
        }
        #pragma unroll
        for (int j = 0; j < 4; j++) {
            int e = tid + j*256;
            int row = e >> 4;
            int ch  = e & 15;
            cp16(smemBase + ((2+buf)*KVT + row*KP + ch*8)*2,
                 &V[(size_t)(kv0+row)*NKV + kh*HD + ch*8]);
        }
    };

    issue_tile(0); cp_commit();
    issue_tile(1); cp_commit();

    const int grow0 = qb*128 + m0 + gid;
    const int grow1 = grow0 + 8;

    for (int kb = 0; kb < nkv; kb++) {
        const int buf = kb & 1;
        const int kv0 = kb * 64;
        cp_wait<1>();
        __syncthreads();

        // ---- S = Q K^T (16 x 64 per warp) ----
        float c[8][4];
        #pragma unroll
        for (int nf = 0; nf < 8; nf++)
            #pragma unroll
            for (int r = 0; r < 4; r++) c[nf][r] = 0.f;

        const __half* Kb = Ks + buf*KVT;
        #pragma unroll
        for (int ks = 0; ks < 8; ks++) {
            int k0 = ks*16 + 2*tig;
            #pragma unroll
            for (int nf = 0; nf < 8; nf++) {
                const __half* bp = Kb + (nf*8+gid)*KP + k0;
                mma_f16(c[nf], qf[ks], ldh(bp), ldh(bp + 8));
            }
        }

        // ---- scale + causal mask ----
        const bool needmask = (kb >= 2*qb);
        #pragma unroll
        for (int nf = 0; nf < 8; nf++) {
            int gc = kv0 + nf*8 + 2*tig;
            c[nf][0] *= scale; c[nf][1] *= scale;
            c[nf][2] *= scale; c[nf][3] *= scale;
            if (needmask) {
                if (gc   > grow0) c[nf][0] = -INFINITY;
                if (gc+1 > grow0) c[nf][1] = -INFINITY;
                if (gc   > grow1) c[nf][2] = -INFINITY;
                if (gc+1 > grow1) c[nf][3] = -INFINITY;
            }
        }

        // ---- online softmax ----
        float mx0 = -INFINITY, mx1 = -INFINITY;
        #pragma unroll
        for (int nf = 0; nf < 8; nf++) {
            mx0 = fmaxf(mx0, fmaxf(c[nf][0], c[nf][1]));
            mx1 = fmaxf(mx1, fmaxf(c[nf][2], c[nf][3]));
        }
        mx0 = fmaxf(mx0, __shfl_xor_sync(0xffffffffu, mx0, 1));
        mx0 = fmaxf(mx0, __shfl_xor_sync(0xffffffffu, mx0, 2));
        mx1 = fmaxf(mx1, __shfl_xor_sync(0xffffffffu, mx1, 1));
        mx1 = fmaxf(mx1, __shfl_xor_sync(0xffffffffu, mx1, 2));

        float mn0 = fmaxf(mrow0, mx0);
        float mn1 = fmaxf(mrow1, mx1);
        float a0 = __expf(mrow0 - mn0);
        float a1 = __expf(mrow1 - mn1);
        mrow0 = mn0; mrow1 = mn1;

        float s0 = 0.f, s1 = 0.f;
        #pragma unroll
        for (int nf = 0; nf < 8; nf++) {
            c[nf][0] = __expf(c[nf][0] - mn0);
            c[nf][1] = __expf(c[nf][1] - mn0);
            c[nf][2] = __expf(c[nf][2] - mn1);
            c[nf][3] = __expf(c[nf][3] - mn1);
            s0 += c[nf][0] + c[nf][1];
            s1 += c[nf][2] + c[nf][3];
        }
        s0 += __shfl_xor_sync(0xffffffffu, s0, 1);
        s0 += __shfl_xor_sync(0xffffffffu, s0, 2);
        s1 += __shfl_xor_sync(0xffffffffu, s1, 1);
        s1 += __shfl_xor_sync(0xffffffffu, s1, 2);
        lrow0 = lrow0*a0 + s0;
        lrow1 = lrow1*a1 + s1;

        #pragma unroll
        for (int nf = 0; nf < 16; nf++) {
            of[nf][0] *= a0; of[nf][1] *= a0;
            of[nf][2] *= a1; of[nf][3] *= a1;
        }

        // ---- P -> smem (half) ----
        {
            __half* pr0 = Ps + (m0+gid)*PP + 2*tig;
            __half* pr1 = pr0 + 8*PP;
            #pragma unroll
            for (int nf = 0; nf < 8; nf++) {
                *(__half2*)(pr0 + nf*8) = __floats2half2_rn(c[nf][0], c[nf][1]);
                *(__half2*)(pr1 + nf*8) = __floats2half2_rn(c[nf][2], c[nf][3]);
            }
        }
        __syncwarp();

        // ---- O += P V  (4 k-steps of 16) ----
        const __half* Vb = Vs + buf*KVT;
        #pragma unroll
        for (int ks = 0; ks < 4; ks++) {
            int k0 = ks*16;
            unsigned a[4];
            const __half* p0 = Ps + (m0+gid)*PP + k0 + 2*tig;
            const __half* p1 = p0 + 8*PP;
            a[0] = ldh(p0);
            a[1] = ldh(p1);
            a[2] = ldh(p0 + 8);
            a[3] = ldh(p1 + 8);
            const __half* vr0 = Vb + (k0 + 2*tig)*KP;       // row k
            #pragma unroll
            for (int nf = 0; nf < 16; nf++) {
                int n = nf*8 + gid;
                unsigned b0 = pack_h2(vr0 + n,          vr0 + KP + n);
                unsigned b1 = pack_h2(vr0 + 8*KP + n,   vr0 + 9*KP + n);
                mma_f16(of[nf], a, b0, b1);
            }
        }

        __syncthreads();
        if (kb + 2 < nkv) issue_tile(kb + 2);
        cp_commit();
    }

    // ---- epilogue: O /= l, write half ----
    float inv0 = 1.f / lrow0;
    float inv1 = 1.f / lrow1;
    #pragma unroll
    for (int nf = 0; nf < 16; nf++) {
        int col = h*HD + nf*8 + 2*tig;
        *(__half2*)&O[(size_t)grow0 * NQ + col] =
            __floats2half2_rn(of[nf][0]*inv0, of[nf][1]*inv0);
        *(__half2*)&O[(size_t)grow1 * NQ + col] =
            __floats2half2_rn(of[nf][2]*inv1, of[nf][3]*inv1);
    }
}

// ---------------------------------------------------------------------------
// Launch
// ---------------------------------------------------------------------------
extern "C" void kernel_launch(void* const* d_in, const int* in_sizes, int n_in,
                              void* d_out, int out_size) {
    const float* x  = (const float*)d_in[0];
    const float* fc = (const float*)d_in[1];
    const float* fs = (const float*)d_in[2];
    const float* wq = (const float*)d_in[3];
    const float* wk = (const float*)d_in[4];
    const float* wv = (const float*)d_in[5];
    const float* wo = (const float*)d_in[6];
    float* out = (float*)d_out;

    __half *Q, *K, *V, *ATT, *Xh, *Wqt, *Wkt, *Wvt, *Wot;
    cudaGetSymbolAddress((void**)&Q,   g_Q);
    cudaGetSymbolAddress((void**)&K,   g_K);
    cudaGetSymbolAddress((void**)&V,   g_V);
    cudaGetSymbolAddress((void**)&ATT, g_attn);
    cudaGetSymbolAddress((void**)&Xh,  g_X);
    cudaGetSymbolAddress((void**)&Wqt, g_Wq);
    cudaGetSymbolAddress((void**)&Wkt, g_Wk);
    cudaGetSymbolAddress((void**)&Wvt, g_Wv);
    cudaGetSymbolAddress((void**)&Wot, g_Wo);

    cudaFuncSetAttribute(flash_f16,
        cudaFuncAttributeMaxDynamicSharedMemorySize, FLASH_SMEM);
    cudaFuncSetAttribute(gemm_f16,
        cudaFuncAttributeMaxDynamicSharedMemorySize, GEMM_SMEM);

    // Prep: x -> half; weights -> transposed half [N][K]
    {
        int n4 = S*Dm/4;
        f2h_kernel<<<(n4+255)/256, 256>>>(x, Xh, n4);
        dim3 blk(32, 8);
        transpose_f2h_kernel<<<dim3(NQ/32,  Dm/32), blk>>>(wq, Wqt, Dm, NQ);
        transpose_f2h_kernel<<<dim3(NKV/32, Dm/32), blk>>>(wk, Wkt, Dm, NKV);
        transpose_f2h_kernel<<<dim3(NKV/32, Dm/32), blk>>>(wv, Wvt, Dm, NKV);
        transpose_f2h_kernel<<<dim3(Dm/32,  NQ/32), blk>>>(wo, Wot, NQ, Dm);
    }

    // QKV projections (fp16 tensor cores, half outputs)
    gemm_f16<<<dim3(NQ/128,  S/128), 256, GEMM_SMEM>>>(S, NQ,  Dm, Xh, Wqt, Q, 1);
    gemm_f16<<<dim3(NKV/128, S/128), 256, GEMM_SMEM>>>(S, NKV, Dm, Xh, Wkt, K, 1);
    gemm_f16<<<dim3(NKV/128, S/128), 256, GEMM_SMEM>>>(S, NKV, Dm, Xh, Wvt, V, 1);

    // RoPE on Q and K
    {
        int total = S * 40 * (HD/2);
        rope_all_kernel<<<(total + 255)/256, 256>>>(Q, K, fc, fs);
    }

    // Causal GQA flash attention (half in/out)
    flash_f16<<<dim3(S/128, HQ), 256, FLASH_SMEM>>>(Q, K, V, ATT);

    // Output projection (fp32 out)
    gemm_f16<<<dim3(Dm/128, S/128), 256, GEMM_SMEM>>>(S, Dm, NQ, ATT, Wot, out, 0);
}

// round 8
// speedup vs baseline: 13.3152x; 1.0575x over previous
#include <cuda_runtime.h>
#include <cuda_fp16.h>
#include <math.h>
#include <stdint.h>

// Problem dims
#define S   2048
#define Dm  4096
#define HQ  32
#define HK  8
#define HD  128
#define NQ  (HQ*HD)   // 4096
#define NKV (HK*HD)   // 1024
#define NQKV (NQ + 2*NKV)  // 6144

// Scratch (device globals; no allocations allowed)
__device__ __half g_Q[S*NQ];            // Q, roped, [S][4096]
__device__ __half g_K[S*NKV];           // K, roped, [S][1024]
__device__ __half g_Vt[NKV*S];          // V transposed: [1024 d][2048 s]
__device__ __half g_attn[S*NQ];         // attention output, [S][4096]
__device__ __half g_X [S*Dm];           // x as half, [S][4096]
__device__ __half g_W6[NQKV*Dm];        // wq|wk|wv transposed: [6144][4096]
__device__ __half g_Wo[Dm*NQ];          // wo transposed: [4096 Dm][4096 NQ]

// ---------------------------------------------------------------------------
// helpers
// ---------------------------------------------------------------------------
__device__ __forceinline__ void mma_f16(float c[4], const unsigned a[4],
                                        unsigned b0, unsigned b1) {
    asm volatile(
        "mma.sync.aligned.m16n8k16.row.col.f32.f16.f16.f32 "
        "{%0,%1,%2,%3}, {%4,%5,%6,%7}, {%8,%9}, {%0,%1,%2,%3};"
        : "+f"(c[0]), "+f"(c[1]), "+f"(c[2]), "+f"(c[3])
        : "r"(a[0]), "r"(a[1]), "r"(a[2]), "r"(a[3]), "r"(b0), "r"(b1));
}

__device__ __forceinline__ void cp16(uint32_t dst, const void* src) {
    asm volatile("cp.async.cg.shared.global [%0], [%1], 16;\n" :: "r"(dst), "l"(src));
}
__device__ __forceinline__ void cp_commit() {
    asm volatile("cp.async.commit_group;\n");
}
template<int N> __device__ __forceinline__ void cp_wait() {
    asm volatile("cp.async.wait_group %0;\n" :: "n"(N));
}

__device__ __forceinline__ unsigned ldh(const __half* p) {   // 4B-aligned half2
    return *(const unsigned*)p;
}

// ---------------------------------------------------------------------------
// Prep: fp32 -> fp16 (vectorized). n4 = n/4.
// ---------------------------------------------------------------------------
__global__ void f2h_kernel(const float* __restrict__ src,
                           __half* __restrict__ dst, int n4) {
    int i = blockIdx.x * blockDim.x + threadIdx.x;
    if (i >= n4) return;
    float4 v = ((const float4*)src)[i];
    *(__half2*)&dst[4*i]     = __floats2half2_rn(v.x, v.y);
    *(__half2*)&dst[4*i + 2] = __floats2half2_rn(v.z, v.w);
}

// ---------------------------------------------------------------------------
// Prep: transpose fp32 [R][C] -> fp16 [C][R]. R,C % 32 == 0.
// ---------------------------------------------------------------------------
__global__ void transpose_f2h_kernel(const float* __restrict__ src,
                                     __half* __restrict__ dst, int R, int C) {
    __shared__ float tile[32][33];
    int c0 = blockIdx.x * 32, r0 = blockIdx.y * 32;
    int x = threadIdx.x, y = threadIdx.y;
    #pragma unroll
    for (int i = y; i < 32; i += 8)
        tile[i][x] = src[(size_t)(r0 + i) * C + c0 + x];
    __syncthreads();
    #pragma unroll
    for (int i = y; i < 32; i += 8)
        dst[(size_t)(c0 + i) * R + r0 + x] = __float2half_rn(tile[x][i]);
}

// ---------------------------------------------------------------------------
// fp16 tensor-core GEMM, cp.async 4-stage pipeline.
// C[M,N] = A[M,K] @ Bt[N,K]^T.  128x128 CTA tile, BK=32, 8 warps 64x32.
// mode 0: write fp32 C.  mode 1: fused QKV epilogue — RoPE for Q/K halves,
//         V written transposed to Vtp[d][s].  (N region per block is uniform
//         since 4096 and 5120 are multiples of 128.)
// ---------------------------------------------------------------------------
#define APITCH 40                 // halves per smem row (32 data + 8 pad)
#define ASZ (128*APITCH)          // 5120 halves
#define GSTAGES 4
#define STAGE_HALVES (2*ASZ)      // 10240 halves
#define GEMM_SMEM (GSTAGES*STAGE_HALVES*2)   // 81920 B

__global__ __launch_bounds__(256)
void gemm_f16(int M, int N, int K,
              const __half* __restrict__ A,
              const __half* __restrict__ Bt,
              void* __restrict__ Cv, int mode,
              __half* __restrict__ Qp, __half* __restrict__ Kp,
              __half* __restrict__ Vtp,
              const float* __restrict__ fc, const float* __restrict__ fs) {
    extern __shared__ __half smh[];
    const uint32_t smemBase = (uint32_t)__cvta_generic_to_shared(smh);

    const int tid  = threadIdx.x;
    const int lane = tid & 31;
    const int wid  = tid >> 5;
    const int gid  = lane >> 2;
    const int tig  = lane & 3;
    const int warpM = wid >> 2;
    const int warpN = wid & 3;
    const int m0 = warpM*64;
    const int n0 = warpN*32;

    const int bx = blockIdx.x;
    const int by = blockIdx.y;

    const __half* Abase = A  + (size_t)(by*128) * K;
    const __half* Bbase = Bt + (size_t)(bx*128) * K;

    auto issue_tile = [&](int t) {
        const int slot = t % GSTAGES;
        const uint32_t stA = smemBase + slot*STAGE_HALVES*2;
        const uint32_t stB = stA + ASZ*2;
        const __half* Ag = Abase + t*32;
        const __half* Bg = Bbase + t*32;
        #pragma unroll
        for (int j = 0; j < 2; j++) {
            int e = tid + j*256;
            int row = e >> 2, ch = e & 3;
            cp16(stA + (row*APITCH + ch*8)*2, Ag + (size_t)row*K + ch*8);
        }
        #pragma unroll
        for (int j = 0; j < 2; j++) {
            int e = tid + j*256;
            int row = e >> 2, ch = e & 3;
            cp16(stB + (row*APITCH + ch*8)*2, Bg + (size_t)row*K + ch*8);
        }
    };

    float c[4][4][4];
    #pragma unroll
    for (int i = 0; i < 4; i++)
        #pragma unroll
        for (int j = 0; j < 4; j++)
            #pragma unroll
            for (int r = 0; r < 4; r++) c[i][j][r] = 0.f;

    const int nt = K / 32;

    #pragma unroll
    for (int t = 0; t < GSTAGES-1; t++) {
        if (t < nt) issue_tile(t);
        cp_commit();
    }

    for (int t = 0; t < nt; t++) {
        cp_wait<GSTAGES-2>();
        __syncthreads();

        if (t + GSTAGES-1 < nt) issue_tile(t + GSTAGES-1);
        cp_commit();

        const int slot = t % GSTAGES;
        const __half* Asl = smh + slot*STAGE_HALVES;
        const __half* Bsl = Asl + ASZ;

        #pragma unroll
        for (int ks = 0; ks < 32; ks += 16) {
            unsigned af[4][4], bf[4][2];
            #pragma unroll
            for (int mf = 0; mf < 4; mf++) {
                const __half* r0p = Asl + (m0 + mf*16 + gid)*APITCH + ks + 2*tig;
                const __half* r1p = r0p + 8*APITCH;
                af[mf][0] = ldh(r0p);
                af[mf][1] = ldh(r1p);
                af[mf][2] = ldh(r0p + 8);
                af[mf][3] = ldh(r1p + 8);
            }
            #pragma unroll
            for (int nf = 0; nf < 4; nf++) {
                const __half* bp = Bsl + (n0 + nf*8 + gid)*APITCH + ks + 2*tig;
                bf[nf][0] = ldh(bp);
                bf[nf][1] = ldh(bp + 8);
            }
            #pragma unroll
            for (int mf = 0; mf < 4; mf++)
                #pragma unroll
                for (int nf = 0; nf < 4; nf++)
                    mma_f16(c[mf][nf], af[mf], bf[nf][0], bf[nf][1]);
        }
    }

    // ---- epilogue ----
    if (mode == 0) {
        float* Cf = (float*)Cv;
        #pragma unroll
        for (int mf = 0; mf < 4; mf++) {
            int row0 = by*128 + m0 + mf*16 + gid;
            #pragma unroll
            for (int nf = 0; nf < 4; nf++) {
                int col = bx*128 + n0 + nf*8 + tig*2;
                *(float2*)&Cf[(size_t)row0 * N + col] =
                    make_float2(c[mf][nf][0], c[mf][nf][1]);
                *(float2*)&Cf[(size_t)(row0+8) * N + col] =
                    make_float2(c[mf][nf][2], c[mf][nf][3]);
            }
        }
    } else {
        // fused QKV epilogue
        #pragma unroll
        for (int mf = 0; mf < 4; mf++) {
            int s0 = by*128 + m0 + mf*16 + gid;
            int s1 = s0 + 8;
            #pragma unroll
            for (int nf = 0; nf < 4; nf++) {
                int gc = bx*128 + n0 + nf*8 + tig*2;
                float v0 = c[mf][nf][0], v1 = c[mf][nf][1];
                float v2 = c[mf][nf][2], v3 = c[mf][nf][3];
                if (gc < NQ) {                      // Q with RoPE
                    int i = (gc & 127) >> 1;
                    float c0 = fc[s0*64+i], sn0 = fs[s0*64+i];
                    float c1 = fc[s1*64+i], sn1 = fs[s1*64+i];
                    *(__half2*)&Qp[(size_t)s0*NQ + gc] =
                        __floats2half2_rn(v0*c0 - v1*sn0, v0*sn0 + v1*c0);
                    *(__half2*)&Qp[(size_t)s1*NQ + gc] =
                        __floats2half2_rn(v2*c1 - v3*sn1, v2*sn1 + v3*c1);
                } else if (gc < NQ + NKV) {         // K with RoPE
                    int d = gc - NQ;
                    int i = (d & 127) >> 1;
                    float c0 = fc[s0*64+i], sn0 = fs[s0*64+i];
                    float c1 = fc[s1*64+i], sn1 = fs[s1*64+i];
                    *(__half2*)&Kp[(size_t)s0*NKV + d] =
                        __floats2half2_rn(v0*c0 - v1*sn0, v0*sn0 + v1*c0);
                    *(__half2*)&Kp[(size_t)s1*NKV + d] =
                        __floats2half2_rn(v2*c1 - v3*sn1, v2*sn1 + v3*c1);
                } else {                            // V, transposed store
                    int d = gc - (NQ + NKV);
                    Vtp[(size_t)d*S + s0]     = __float2half_rn(v0);
                    Vtp[(size_t)(d+1)*S + s0] = __float2half_rn(v1);
                    Vtp[(size_t)d*S + s1]     = __float2half_rn(v2);
                    Vtp[(size_t)(d+1)*S + s1] = __float2half_rn(v3);
                }
            }
        }
    }
}

// ---------------------------------------------------------------------------
// Flash attention, fp16 MMA. BQ=128, BKV=64. 8 warps, warp w owns q-rows
// w*16..w*16+15. Causal, GQA (4 q heads per kv head).
// K smem: [2][64 kv][KP=136 d]; V smem TRANSPOSED: [2][128 d][VP=72 kv].
// ---------------------------------------------------------------------------
#define KP 136
#define VP 72
#define PP 72
#define KVT (64*KP)               // 8704 halves per K buffer
#define VTT (128*VP)              // 9216 halves per V buffer
#define PS_OFF (2*KVT + 2*VTT)    // 35840
#define FLASH_SMEM ((PS_OFF + 128*PP) * 2)   // 90112 B

__global__ __launch_bounds__(256)
void flash_f16(const __half* __restrict__ Q,
               const __half* __restrict__ K,
               const __half* __restrict__ Vt,
               __half* __restrict__ O) {
    extern __shared__ __half smh[];
    __half* Ks  = smh;                    // [2][64][KP]
    __half* Vts = smh + 2*KVT;            // [2][128][VP]
    __half* Ps  = smh + PS_OFF;           // [128][PP]

    const int qb  = gridDim.x - 1 - blockIdx.x;   // heavy blocks first
    const int h   = blockIdx.y;
    const int kh  = h >> 2;
    const int tid = threadIdx.x;
    const int lane = tid & 31;
    const int wid  = tid >> 5;
    const int gid  = lane >> 2;
    const int tig  = lane & 3;
    const int m0   = wid * 16;
    const float scale = 0.08838834764831845f;

    const uint32_t smemBase = (uint32_t)__cvta_generic_to_shared(smh);
    const __half* Vkh = Vt + (size_t)(kh*HD) * S;   // this kv-head's Vt rows

    // Stage Q tile (128 x 128 halves) into Ks area (pitch KP), grab frags
    #pragma unroll
    for (int i = 0; i < 8; i++) {
        int e = tid + i*256;
        int row = e >> 4;
        int ch  = e & 15;
        *(float4*)&Ks[row*KP + ch*8] =
            *(const float4*)&Q[(size_t)(qb*128 + row)*NQ + h*HD + ch*8];
    }
    __syncthreads();

    unsigned qf[8][4];
    {
        const __half* q0 = Ks + (m0 + gid)*KP;
        const __half* q1 = q0 + 8*KP;
        #pragma unroll
        for (int ks = 0; ks < 8; ks++) {
            int k0 = ks*16 + 2*tig;
            qf[ks][0] = ldh(q0 + k0);
            qf[ks][1] = ldh(q1 + k0);
            qf[ks][2] = ldh(q0 + k0 + 8);
            qf[ks][3] = ldh(q1 + k0 + 8);
        }
    }
    __syncthreads();

    float of[16][4];
    #pragma unroll
    for (int n = 0; n < 16; n++)
        #pragma unroll
        for (int r = 0; r < 4; r++) of[n][r] = 0.f;
    float mrow0 = -INFINITY, mrow1 = -INFINITY;
    float lrow0 = 0.f, lrow1 = 0.f;

    const int nkv = 2*qb + 2;

    auto issue_tile = [&](int kb) {
        int buf = kb & 1;
        int kv0 = kb * 64;
        // K: 64 rows x 128 d -> pitch KP
        #pragma unroll
        for (int j = 0; j < 4; j++) {
            int e = tid + j*256;
            int row = e >> 4;
            int ch  = e & 15;
            cp16(smemBase + (buf*KVT + row*KP + ch*8)*2,
                 &K[(size_t)(kv0+row)*NKV + kh*HD + ch*8]);
        }
        // V: 128 d-rows x 64 kv -> pitch VP
        #pragma unroll
        for (int j = 0; j < 4; j++) {
            int e = tid + j*256;
            int d  = e >> 3;
            int ch = e & 7;
            cp16(smemBase + (2*KVT + buf*VTT + d*VP + ch*8)*2,
                 &Vkh[(size_t)d*S + kv0 + ch*8]);
        }
    };

    issue_tile(0); cp_commit();
    issue_tile(1); cp_commit();

    const int grow0 = qb*128 + m0 + gid;
    const int grow1 = grow0 + 8;

    for (int kb = 0; kb < nkv; kb++) {
        const int buf = kb & 1;
        const int kv0 = kb * 64;
        cp_wait<1>();
        __syncthreads();

        // ---- S = Q K^T (16 x 64 per warp) ----
        float c[8][4];
        #pragma unroll
        for (int nf = 0; nf < 8; nf++)
            #pragma unroll
            for (int r = 0; r < 4; r++) c[nf][r] = 0.f;

        const __half* Kb = Ks + buf*KVT;
        #pragma unroll
        for (int ks = 0; ks < 8; ks++) {
            int k0 = ks*16 + 2*tig;
            #pragma unroll
            for (int nf = 0; nf < 8; nf++) {
                const __half* bp = Kb + (nf*8+gid)*KP + k0;
                mma_f16(c[nf], qf[ks], ldh(bp), ldh(bp + 8));
            }
        }

        // ---- scale + causal mask ----
        const bool needmask = (kb >= 2*qb);
        #pragma unroll
        for (int nf = 0; nf < 8; nf++) {
            int gc = kv0 + nf*8 + 2*tig;
            c[nf][0] *= scale; c[nf][1] *= scale;
            c[nf][2] *= scale; c[nf][3] *= scale;
            if (needmask) {
                if (gc   > grow0) c[nf][0] = -INFINITY;
                if (gc+1 > grow0) c[nf][1] = -INFINITY;
                if (gc   > grow1) c[nf][2] = -INFINITY;
                if (gc+1 > grow1) c[nf][3] = -INFINITY;
            }
        }

        // ---- online softmax ----
        float mx0 = -INFINITY, mx1 = -INFINITY;
        #pragma unroll
        for (int nf = 0; nf < 8; nf++) {
            mx0 = fmaxf(mx0, fmaxf(c[nf][0], c[nf][1]));
            mx1 = fmaxf(mx1, fmaxf(c[nf][2], c[nf][3]));
        }
        mx0 = fmaxf(mx0, __shfl_xor_sync(0xffffffffu, mx0, 1));
        mx0 = fmaxf(mx0, __shfl_xor_sync(0xffffffffu, mx0, 2));
        mx1 = fmaxf(mx1, __shfl_xor_sync(0xffffffffu, mx1, 1));
        mx1 = fmaxf(mx1, __shfl_xor_sync(0xffffffffu, mx1, 2));

        float mn0 = fmaxf(mrow0, mx0);
        float mn1 = fmaxf(mrow1, mx1);
        float a0 = __expf(mrow0 - mn0);
        float a1 = __expf(mrow1 - mn1);
        mrow0 = mn0; mrow1 = mn1;

        float s0 = 0.f, s1 = 0.f;
        #pragma unroll
        for (int nf = 0; nf < 8; nf++) {
            c[nf][0] = __expf(c[nf][0] - mn0);
            c[nf][1] = __expf(c[nf][1] - mn0);
            c[nf][2] = __expf(c[nf][2] - mn1);
            c[nf][3] = __expf(c[nf][3] - mn1);
            s0 += c[nf][0] + c[nf][1];
            s1 += c[nf][2] + c[nf][3];
        }
        s0 += __shfl_xor_sync(0xffffffffu, s0, 1);
        s0 += __shfl_xor_sync(0xffffffffu, s0, 2);
        s1 += __shfl_xor_sync(0xffffffffu, s1, 1);
        s1 += __shfl_xor_sync(0xffffffffu, s1, 2);
        lrow0 = lrow0*a0 + s0;
        lrow1 = lrow1*a1 + s1;

        #pragma unroll
        for (int nf = 0; nf < 16; nf++) {
            of[nf][0] *= a0; of[nf][1] *= a0;
            of[nf][2] *= a1; of[nf][3] *= a1;
        }

        // ---- P -> smem (half) ----
        {
            __half* pr0 = Ps + (m0+gid)*PP + 2*tig;
            __half* pr1 = pr0 + 8*PP;
            #pragma unroll
            for (int nf = 0; nf < 8; nf++) {
                *(__half2*)(pr0 + nf*8) = __floats2half2_rn(c[nf][0], c[nf][1]);
                *(__half2*)(pr1 + nf*8) = __floats2half2_rn(c[nf][2], c[nf][3]);
            }
        }
        __syncwarp();

        // ---- O += P V  (4 k-steps of 16; B-frags contiguous from Vts) ----
        const __half* Vb = Vts + buf*VTT;
        #pragma unroll
        for (int ks = 0; ks < 4; ks++) {
            int k0 = ks*16;
            unsigned a[4];
            const __half* p0 = Ps + (m0+gid)*PP + k0 + 2*tig;
            const __half* p1 = p0 + 8*PP;
            a[0] = ldh(p0);
            a[1] = ldh(p1);
            a[2] = ldh(p0 + 8);
            a[3] = ldh(p1 + 8);
            #pragma unroll
            for (int nf = 0; nf < 16; nf++) {
                const __half* bp = Vb + (nf*8+gid)*VP + k0 + 2*tig;
                mma_f16(of[nf], a, ldh(bp), ldh(bp + 8));
            }
        }

        __syncthreads();
        if (kb + 2 < nkv) issue_tile(kb + 2);
        cp_commit();
    }

    // ---- epilogue: O /= l, write half ----
    float inv0 = 1.f / lrow0;
    float inv1 = 1.f / lrow1;
    #pragma unroll
    for (int nf = 0; nf < 16; nf++) {
        int col = h*HD + nf*8 + 2*tig;
        *(__half2*)&O[(size_t)grow0 * NQ + col] =
            __floats2half2_rn(of[nf][0]*inv0, of[nf][1]*inv0);
        *(__half2*)&O[(size_t)grow1 * NQ + col] =
            __floats2half2_rn(of[nf][2]*inv1, of[nf][3]*inv1);
    }
}

// ---------------------------------------------------------------------------
// Launch
// ---------------------------------------------------------------------------
extern "C" void kernel_launch(void* const* d_in, const int* in_sizes, int n_in,
                              void* d_out, int out_size) {
    const float* x  = (const float*)d_in[0];
    const float* fc = (const float*)d_in[1];
    const float* fs = (const float*)d_in[2];
    const float* wq = (const float*)d_in[3];
    const float* wk = (const float*)d_in[4];
    const float* wv = (const float*)d_in[5];
    const float* wo = (const float*)d_in[6];
    float* out = (float*)d_out;

    __half *Q, *K, *Vt, *ATT, *Xh, *W6, *Wot;
    cudaGetSymbolAddress((void**)&Q,   g_Q);
    cudaGetSymbolAddress((void**)&K,   g_K);
    cudaGetSymbolAddress((void**)&Vt,  g_Vt);
    cudaGetSymbolAddress((void**)&ATT, g_attn);
    cudaGetSymbolAddress((void**)&Xh,  g_X);
    cudaGetSymbolAddress((void**)&W6,  g_W6);
    cudaGetSymbolAddress((void**)&Wot, g_Wo);

    cudaFuncSetAttribute(flash_f16,
        cudaFuncAttributeMaxDynamicSharedMemorySize, FLASH_SMEM);
    cudaFuncSetAttribute(gemm_f16,
        cudaFuncAttributeMaxDynamicSharedMemorySize, GEMM_SMEM);

    // Prep: x -> half; weights -> transposed half, QKV concatenated
    {
        int n4 = S*Dm/4;
        f2h_kernel<<<(n4+255)/256, 256>>>(x, Xh, n4);
        dim3 blk(32, 8);
        transpose_f2h_kernel<<<dim3(NQ/32,  Dm/32), blk>>>(wq, W6, Dm, NQ);
        transpose_f2h_kernel<<<dim3(NKV/32, Dm/32), blk>>>(wk, W6 + (size_t)NQ*Dm, Dm, NKV);
        transpose_f2h_kernel<<<dim3(NKV/32, Dm/32), blk>>>(wv, W6 + (size_t)(NQ+NKV)*Dm, Dm, NKV);
        transpose_f2h_kernel<<<dim3(Dm/32,  NQ/32), blk>>>(wo, Wot, NQ, Dm);
    }

    // Fused QKV projection + RoPE (+ V transpose)
    gemm_f16<<<dim3(NQKV/128, S/128), 256, GEMM_SMEM>>>(
        S, NQKV, Dm, Xh, W6, nullptr, 1, Q, K, Vt, fc, fs);

    // Causal GQA flash attention (half in/out)
    flash_f16<<<dim3(S/128, HQ), 256, FLASH_SMEM>>>(Q, K, Vt, ATT);

    // Output projection (fp32 out)
    gemm_f16<<<dim3(Dm/128, S/128), 256, GEMM_SMEM>>>(
        S, Dm, NQ, ATT, Wot, out, 0, nullptr, nullptr, nullptr, nullptr, nullptr);
}

// round 9
// speedup vs baseline: 15.7670x; 1.1841x over previous
#include <cuda_runtime.h>
#include <cuda_fp16.h>
#include <math.h>
#include <stdint.h>

// Problem dims
#define S   2048
#define Dm  4096
#define HQ  32
#define HK  8
#define HD  128
#define NQ  (HQ*HD)   // 4096
#define NKV (HK*HD)   // 1024
#define NQKV (NQ + 2*NKV)  // 6144

// Scratch (device globals; no allocations allowed)
__device__ __half g_Q[S*NQ];            // Q, roped, [S][4096]
__device__ __half g_K[S*NKV];           // K, roped, [S][1024]
__device__ __half g_Vt[NKV*S];          // V transposed: [1024 d][2048 s]
__device__ __half g_attn[S*NQ];         // attention output, [S][4096]
__device__ __half g_X [S*Dm];           // x as half, [S][4096]
__device__ __half g_W6[NQKV*Dm];        // wq|wk|wv transposed: [6144][4096]
__device__ __half g_Wo[Dm*NQ];          // wo transposed: [4096][4096]

// ---------------------------------------------------------------------------
// helpers
// ---------------------------------------------------------------------------
__device__ __forceinline__ void mma_f16(float c[4], const unsigned a[4],
                                        unsigned b0, unsigned b1) {
    asm volatile(
        "mma.sync.aligned.m16n8k16.row.col.f32.f16.f16.f32 "
        "{%0,%1,%2,%3}, {%4,%5,%6,%7}, {%8,%9}, {%0,%1,%2,%3};"
        : "+f"(c[0]), "+f"(c[1]), "+f"(c[2]), "+f"(c[3])
        : "r"(a[0]), "r"(a[1]), "r"(a[2]), "r"(a[3]), "r"(b0), "r"(b1));
}

__device__ __forceinline__ void ldsm4(unsigned& r0, unsigned& r1,
                                      unsigned& r2, unsigned& r3, uint32_t addr) {
    asm volatile("ldmatrix.sync.aligned.m8n8.x4.shared.b16 {%0,%1,%2,%3}, [%4];"
                 : "=r"(r0), "=r"(r1), "=r"(r2), "=r"(r3) : "r"(addr));
}

__device__ __forceinline__ void cp16(uint32_t dst, const void* src) {
    asm volatile("cp.async.cg.shared.global [%0], [%1], 16;\n" :: "r"(dst), "l"(src));
}
__device__ __forceinline__ void cp_commit() {
    asm volatile("cp.async.commit_group;\n");
}
template<int N> __device__ __forceinline__ void cp_wait() {
    asm volatile("cp.async.wait_group %0;\n" :: "n"(N));
}

// ---------------------------------------------------------------------------
// Mega-prep: one launch does x->half and all 4 weight transposes.
// Region dispatch by linear block id.
// ---------------------------------------------------------------------------
#define RB_WQ 16384    // (NQ/32)*(Dm/32)  = 128*128
#define RB_WK 4096     // (NKV/32)*(Dm/32) = 32*128
#define RB_WV 4096
#define RB_WO 16384    // (Dm/32)*(NQ/32)
#define RB_X  2048
#define PREP_BLOCKS (RB_WQ + RB_WK + RB_WV + RB_WO + RB_X)

__device__ __forceinline__ void transp_f2h(const float* __restrict__ src,
                                           __half* __restrict__ dst,
                                           int R, int C, int bx, int by, int tid,
                                           float (*tile)[33]) {
    int c0 = bx*32, r0 = by*32;
    int x = tid & 31, y = tid >> 5;    // y: 0..7
    #pragma unroll
    for (int i = y; i < 32; i += 8)
        tile[i][x] = src[(size_t)(r0 + i) * C + c0 + x];
    __syncthreads();
    #pragma unroll
    for (int i = y; i < 32; i += 8)
        dst[(size_t)(c0 + i) * R + r0 + x] = __float2half_rn(tile[x][i]);
}

__global__ __launch_bounds__(256)
void prep_kernel(const float* __restrict__ x,
                 const float* __restrict__ wq, const float* __restrict__ wk,
                 const float* __restrict__ wv, const float* __restrict__ wo,
                 __half* __restrict__ Xh, __half* __restrict__ W6,
                 __half* __restrict__ Wot) {
    __shared__ float tile[32][33];
    int bid = blockIdx.x;
    int tid = threadIdx.x;
    if (bid < RB_WQ) {
        transp_f2h(wq, W6, Dm, NQ, bid % 128, bid / 128, tid, tile);
        return;
    }
    bid -= RB_WQ;
    if (bid < RB_WK) {
        transp_f2h(wk, W6 + (size_t)NQ*Dm, Dm, NKV, bid % 32, bid / 32, tid, tile);
        return;
    }
    bid -= RB_WK;
    if (bid < RB_WV) {
        transp_f2h(wv, W6 + (size_t)(NQ+NKV)*Dm, Dm, NKV, bid % 32, bid / 32, tid, tile);
        return;
    }
    bid -= RB_WV;
    if (bid < RB_WO) {
        transp_f2h(wo, Wot, NQ, Dm, bid % 128, bid / 128, tid, tile);
        return;
    }
    bid -= RB_WO;
    // x -> half: block handles 1024 float4
    {
        const float4* src4 = (const float4*)x;
        #pragma unroll
        for (int j = 0; j < 4; j++) {
            int i = bid*1024 + tid + j*256;
            float4 v = src4[i];
            *(__half2*)&Xh[4*i]     = __floats2half2_rn(v.x, v.y);
            *(__half2*)&Xh[4*i + 2] = __floats2half2_rn(v.z, v.w);
        }
    }
}

// ---------------------------------------------------------------------------
// fp16 tensor-core GEMM, cp.async 4-stage pipeline, ldmatrix fragments.
// C[M,N] = A[M,K] @ Bt[N,K]^T.  128x128 CTA tile, BK=32, 8 warps 64x32.
// mode 0: write fp32 C.  mode 1: fused QKV epilogue (RoPE Q/K, V transposed).
// ---------------------------------------------------------------------------
#define APITCH 40                 // halves per smem row (32 data + 8 pad)
#define ASZ (128*APITCH)          // 5120 halves
#define GSTAGES 4
#define STAGE_HALVES (2*ASZ)      // 10240 halves
#define GEMM_SMEM (GSTAGES*STAGE_HALVES*2)   // 81920 B

__global__ __launch_bounds__(256)
void gemm_f16(int M, int N, int K,
              const __half* __restrict__ A,
              const __half* __restrict__ Bt,
              void* __restrict__ Cv, int mode,
              __half* __restrict__ Qp, __half* __restrict__ Kp,
              __half* __restrict__ Vtp,
              const float* __restrict__ fc, const float* __restrict__ fs) {
    extern __shared__ __half smh[];
    const uint32_t smemBase = (uint32_t)__cvta_generic_to_shared(smh);

    const int tid  = threadIdx.x;
    const int lane = tid & 31;
    const int wid  = tid >> 5;
    const int gid  = lane >> 2;
    const int tig  = lane & 3;
    const int warpM = wid >> 2;
    const int warpN = wid & 3;
    const int m0 = warpM*64;
    const int n0 = warpN*32;

    // ldmatrix lane address patterns (bytes)
    const int g8 = lane >> 3, r8 = lane & 7;
    const int laneA = ((((g8 & 1) << 3) + r8) * APITCH + ((g8 >> 1) << 3)) * 2;
    const int laneB = ((((g8 >> 1) << 3) + r8) * APITCH + ((g8 & 1) << 3)) * 2;

    const int bx = blockIdx.x;
    const int by = blockIdx.y;

    const __half* Abase = A  + (size_t)(by*128) * K;
    const __half* Bbase = Bt + (size_t)(bx*128) * K;

    auto issue_tile = [&](int t) {
        const int slot = t % GSTAGES;
        const uint32_t stA = smemBase + slot*STAGE_HALVES*2;
        const uint32_t stB = stA + ASZ*2;
        const __half* Ag = Abase + t*32;
        const __half* Bg = Bbase + t*32;
        #pragma unroll
        for (int j = 0; j < 2; j++) {
            int e = tid + j*256;
            int row = e >> 2, ch = e & 3;
            cp16(stA + (row*APITCH + ch*8)*2, Ag + (size_t)row*K + ch*8);
        }
        #pragma unroll
        for (int j = 0; j < 2; j++) {
            int e = tid + j*256;
            int row = e >> 2, ch = e & 3;
            cp16(stB + (row*APITCH + ch*8)*2, Bg + (size_t)row*K + ch*8);
        }
    };

    float c[4][4][4];
    #pragma unroll
    for (int i = 0; i < 4; i++)
        #pragma unroll
        for (int j = 0; j < 4; j++)
            #pragma unroll
            for (int r = 0; r < 4; r++) c[i][j][r] = 0.f;

    const int nt = K / 32;

    #pragma unroll
    for (int t = 0; t < GSTAGES-1; t++) {
        if (t < nt) issue_tile(t);
        cp_commit();
    }

    for (int t = 0; t < nt; t++) {
        cp_wait<GSTAGES-2>();
        __syncthreads();

        if (t + GSTAGES-1 < nt) issue_tile(t + GSTAGES-1);
        cp_commit();

        const int slot = t % GSTAGES;
        const uint32_t slotA = smemBase + slot*STAGE_HALVES*2;
        const uint32_t slotB = slotA + ASZ*2;

        #pragma unroll
        for (int ks = 0; ks < 32; ks += 16) {
            unsigned af[4][4], bf[4][2];
            #pragma unroll
            for (int mf = 0; mf < 4; mf++)
                ldsm4(af[mf][0], af[mf][1], af[mf][2], af[mf][3],
                      slotA + ((m0 + mf*16)*APITCH + ks)*2 + laneA);
            #pragma unroll
            for (int nf2 = 0; nf2 < 4; nf2 += 2)
                ldsm4(bf[nf2][0], bf[nf2][1], bf[nf2+1][0], bf[nf2+1][1],
                      slotB + ((n0 + nf2*8)*APITCH + ks)*2 + laneB);
            #pragma unroll
            for (int mf = 0; mf < 4; mf++)
                #pragma unroll
                for (int nf = 0; nf < 4; nf++)
                    mma_f16(c[mf][nf], af[mf], bf[nf][0], bf[nf][1]);
        }
    }

    // ---- epilogue ----
    if (mode == 0) {
        float* Cf = (float*)Cv;
        #pragma unroll
        for (int mf = 0; mf < 4; mf++) {
            int row0 = by*128 + m0 + mf*16 + gid;
            #pragma unroll
            for (int nf = 0; nf < 4; nf++) {
                int col = bx*128 + n0 + nf*8 + tig*2;
                *(float2*)&Cf[(size_t)row0 * N + col] =
                    make_float2(c[mf][nf][0], c[mf][nf][1]);
                *(float2*)&Cf[(size_t)(row0+8) * N + col] =
                    make_float2(c[mf][nf][2], c[mf][nf][3]);
            }
        }
    } else {
        #pragma unroll
        for (int mf = 0; mf < 4; mf++) {
            int s0 = by*128 + m0 + mf*16 + gid;
            int s1 = s0 + 8;
            #pragma unroll
            for (int nf = 0; nf < 4; nf++) {
                int gc = bx*128 + n0 + nf*8 + tig*2;
                float v0 = c[mf][nf][0], v1 = c[mf][nf][1];
                float v2 = c[mf][nf][2], v3 = c[mf][nf][3];
                if (gc < NQ) {                      // Q with RoPE
                    int i = (gc & 127) >> 1;
                    float c0 = fc[s0*64+i], sn0 = fs[s0*64+i];
                    float c1 = fc[s1*64+i], sn1 = fs[s1*64+i];
                    *(__half2*)&Qp[(size_t)s0*NQ + gc] =
                        __floats2half2_rn(v0*c0 - v1*sn0, v0*sn0 + v1*c0);
                    *(__half2*)&Qp[(size_t)s1*NQ + gc] =
                        __floats2half2_rn(v2*c1 - v3*sn1, v2*sn1 + v3*c1);
                } else if (gc < NQ + NKV) {         // K with RoPE
                    int d = gc - NQ;
                    int i = (d & 127) >> 1;
                    float c0 = fc[s0*64+i], sn0 = fs[s0*64+i];
                    float c1 = fc[s1*64+i], sn1 = fs[s1*64+i];
                    *(__half2*)&Kp[(size_t)s0*NKV + d] =
                        __floats2half2_rn(v0*c0 - v1*sn0, v0*sn0 + v1*c0);
                    *(__half2*)&Kp[(size_t)s1*NKV + d] =
                        __floats2half2_rn(v2*c1 - v3*sn1, v2*sn1 + v3*c1);
                } else {                            // V, transposed store
                    int d = gc - (NQ + NKV);
                    Vtp[(size_t)d*S + s0]     = __float2half_rn(v0);
                    Vtp[(size_t)(d+1)*S + s0] = __float2half_rn(v1);
                    Vtp[(size_t)d*S + s1]     = __float2half_rn(v2);
                    Vtp[(size_t)(d+1)*S + s1] = __float2half_rn(v3);
                }
            }
        }
    }
}

// ---------------------------------------------------------------------------
// Flash attention, fp16 MMA + ldmatrix. BQ=128, BKV=64. 8 warps.
// K smem [2][64 kv][KP d]; V smem transposed [2][128 d][VP kv]; P [128][PP].
// ---------------------------------------------------------------------------
#define KP 136
#define VP 72
#define PP 72
#define KVT (64*KP)
#define VTT (128*VP)
#define PS_OFF (2*KVT + 2*VTT)
#define FLASH_SMEM ((PS_OFF + 128*PP) * 2)   // 90112 B

__global__ __launch_bounds__(256)
void flash_f16(const __half* __restrict__ Q,
               const __half* __restrict__ K,
               const __half* __restrict__ Vt,
               __half* __restrict__ O) {
    extern __shared__ __half smh[];
    __half* Ks  = smh;                    // [2][64][KP]
    __half* Ps  = smh + PS_OFF;           // [128][PP]

    const int qb  = gridDim.x - 1 - blockIdx.x;
    const int h   = blockIdx.y;
    const int kh  = h >> 2;
    const int tid = threadIdx.x;
    const int lane = tid & 31;
    const int wid  = tid >> 5;
    const int gid  = lane >> 2;
    const int tig  = lane & 3;
    const int m0   = wid * 16;
    const float scale = 0.08838834764831845f;

    const uint32_t smemBase = (uint32_t)__cvta_generic_to_shared(smh);
    const __half* Vkh = Vt + (size_t)(kh*HD) * S;

    const int g8 = lane >> 3, r8 = lane & 7;
    const int laneAK = ((((g8 & 1) << 3) + r8) * KP + ((g8 >> 1) << 3)) * 2;
    const int laneBK = ((((g8 >> 1) << 3) + r8) * KP + ((g8 & 1) << 3)) * 2;
    const int laneAP = ((((g8 & 1) << 3) + r8) * PP + ((g8 >> 1) << 3)) * 2;
    const int laneBV = ((((g8 >> 1) << 3) + r8) * VP + ((g8 & 1) << 3)) * 2;

    // Stage Q tile into Ks area (pitch KP), grab fragments via ldmatrix
    #pragma unroll
    for (int i = 0; i < 8; i++) {
        int e = tid + i*256;
        int row = e >> 4;
        int ch  = e & 15;
        *(float4*)&Ks[row*KP + ch*8] =
            *(const float4*)&Q[(size_t)(qb*128 + row)*NQ + h*HD + ch*8];
    }
    __syncthreads();

    unsigned qf[8][4];
    #pragma unroll
    for (int ks = 0; ks < 8; ks++)
        ldsm4(qf[ks][0], qf[ks][1], qf[ks][2], qf[ks][3],
              smemBase + (m0*KP + ks*16)*2 + laneAK);
    __syncthreads();

    float of[16][4];
    #pragma unroll
    for (int n = 0; n < 16; n++)
        #pragma unroll
        for (int r = 0; r < 4; r++) of[n][r] = 0.f;
    float mrow0 = -INFINITY, mrow1 = -INFINITY;
    float lrow0 = 0.f, lrow1 = 0.f;

    const int nkv = 2*qb + 2;

    auto issue_tile = [&](int kb) {
        int buf = kb & 1;
        int kv0 = kb * 64;
        #pragma unroll
        for (int j = 0; j < 4; j++) {
            int e = tid + j*256;
            int row = e >> 4;
            int ch  = e & 15;
            cp16(smemBase + (buf*KVT + row*KP + ch*8)*2,
                 &K[(size_t)(kv0+row)*NKV + kh*HD + ch*8]);
        }
        #pragma unroll
        for (int j = 0; j < 4; j++) {
            int e = tid + j*256;
            int d  = e >> 3;
            int ch = e & 7;
            cp16(smemBase + (2*KVT + buf*VTT + d*VP + ch*8)*2,
                 &Vkh[(size_t)d*S + kv0 + ch*8]);
        }
    };

    issue_tile(0); cp_commit();
    issue_tile(1); cp_commit();

    const int grow0 = qb*128 + m0 + gid;
    const int grow1 = grow0 + 8;

    for (int kb = 0; kb < nkv; kb++) {
        const int buf = kb & 1;
        const int kv0 = kb * 64;
        cp_wait<1>();
        __syncthreads();

        // ---- S = Q K^T ----
        float c[8][4];
        #pragma unroll
        for (int nf = 0; nf < 8; nf++)
            #pragma unroll
            for (int r = 0; r < 4; r++) c[nf][r] = 0.f;

        const uint32_t kbAddr = smemBase + buf*KVT*2;
        #pragma unroll
        for (int ks = 0; ks < 8; ks++) {
            #pragma unroll
            for (int nf2 = 0; nf2 < 8; nf2 += 2) {
                unsigned b0, b1, b2, b3;
                ldsm4(b0, b1, b2, b3, kbAddr + (nf2*8*KP + ks*16)*2 + laneBK);
                mma_f16(c[nf2],   qf[ks], b0, b1);
                mma_f16(c[nf2+1], qf[ks], b2, b3);
            }
        }

        // ---- scale + causal mask ----
        const bool needmask = (kb >= 2*qb);
        #pragma unroll
        for (int nf = 0; nf < 8; nf++) {
            int gc = kv0 + nf*8 + 2*tig;
            c[nf][0] *= scale; c[nf][1] *= scale;
            c[nf][2] *= scale; c[nf][3] *= scale;
            if (needmask) {
                if (gc   > grow0) c[nf][0] = -INFINITY;
                if (gc+1 > grow0) c[nf][1] = -INFINITY;
                if (gc   > grow1) c[nf][2] = -INFINITY;
                if (gc+1 > grow1) c[nf][3] = -INFINITY;
            }
        }

        // ---- online softmax ----
        float mx0 = -INFINITY, mx1 = -INFINITY;
        #pragma unroll
        for (int nf = 0; nf < 8; nf++) {
            mx0 = fmaxf(mx0, fmaxf(c[nf][0], c[nf][1]));
            mx1 = fmaxf(mx1, fmaxf(c[nf][2], c[nf][3]));
        }
        mx0 = fmaxf(mx0, __shfl_xor_sync(0xffffffffu, mx0, 1));
        mx0 = fmaxf(mx0, __shfl_xor_sync(0xffffffffu, mx0, 2));
        mx1 = fmaxf(mx1, __shfl_xor_sync(0xffffffffu, mx1, 1));
        mx1 = fmaxf(mx1, __shfl_xor_sync(0xffffffffu, mx1, 2));

        float mn0 = fmaxf(mrow0, mx0);
        float mn1 = fmaxf(mrow1, mx1);
        float a0 = __expf(mrow0 - mn0);
        float a1 = __expf(mrow1 - mn1);
        mrow0 = mn0; mrow1 = mn1;

        float s0 = 0.f, s1 = 0.f;
        #pragma unroll
        for (int nf = 0; nf < 8; nf++) {
            c[nf][0] = __expf(c[nf][0] - mn0);
            c[nf][1] = __expf(c[nf][1] - mn0);
            c[nf][2] = __expf(c[nf][2] - mn1);
            c[nf][3] = __expf(c[nf][3] - mn1);
            s0 += c[nf][0] + c[nf][1];
            s1 += c[nf][2] + c[nf][3];
        }
        s0 += __shfl_xor_sync(0xffffffffu, s0, 1);
        s0 += __shfl_xor_sync(0xffffffffu, s0, 2);
        s1 += __shfl_xor_sync(0xffffffffu, s1, 1);
        s1 += __shfl_xor_sync(0xffffffffu, s1, 2);
        lrow0 = lrow0*a0 + s0;
        lrow1 = lrow1*a1 + s1;

        #pragma unroll
        for (int nf = 0; nf < 16; nf++) {
            of[nf][0] *= a0; of[nf][1] *= a0;
            of[nf][2] *= a1; of[nf][3] *= a1;
        }

        // ---- P -> smem (half) ----
        {
            __half* pr0 = Ps + (m0+gid)*PP + 2*tig;
            __half* pr1 = pr0 + 8*PP;
            #pragma unroll
            for (int nf = 0; nf < 8; nf++) {
                *(__half2*)(pr0 + nf*8) = __floats2half2_rn(c[nf][0], c[nf][1]);
                *(__half2*)(pr1 + nf*8) = __floats2half2_rn(c[nf][2], c[nf][3]);
            }
        }
        __syncwarp();

        // ---- O += P V (ldmatrix frags) ----
        const uint32_t psAddr = smemBase + PS_OFF*2;
        const uint32_t vbAddr = smemBase + (2*KVT + buf*VTT)*2;
        #pragma unroll
        for (int ks = 0; ks < 4; ks++) {
            unsigned a[4];
            ldsm4(a[0], a[1], a[2], a[3],
                  psAddr + (m0*PP + ks*16)*2 + laneAP);
            #pragma unroll
            for (int nf2 = 0; nf2 < 16; nf2 += 2) {
                unsigned b0, b1, b2, b3;
                ldsm4(b0, b1, b2, b3, vbAddr + (nf2*8*VP + ks*16)*2 + laneBV);
                mma_f16(of[nf2],   a, b0, b1);
                mma_f16(of[nf2+1], a, b2, b3);
            }
        }

        __syncthreads();
        if (kb + 2 < nkv) issue_tile(kb + 2);
        cp_commit();
    }

    // ---- epilogue: O /= l, write half ----
    float inv0 = 1.f / lrow0;
    float inv1 = 1.f / lrow1;
    #pragma unroll
    for (int nf = 0; nf < 16; nf++) {
        int col = h*HD + nf*8 + 2*tig;
        *(__half2*)&O[(size_t)grow0 * NQ + col] =
            __floats2half2_rn(of[nf][0]*inv0, of[nf][1]*inv0);
        *(__half2*)&O[(size_t)grow1 * NQ + col] =
            __floats2half2_rn(of[nf][2]*inv1, of[nf][3]*inv1);
    }
}

// ---------------------------------------------------------------------------
// Launch
// ---------------------------------------------------------------------------
extern "C" void kernel_launch(void* const* d_in, const int* in_sizes, int n_in,
                              void* d_out, int out_size) {
    const float* x  = (const float*)d_in[0];
    const float* fc = (const float*)d_in[1];
    const float* fs = (const float*)d_in[2];
    const float* wq = (const float*)d_in[3];
    const float* wk = (const float*)d_in[4];
    const float* wv = (const float*)d_in[5];
    const float* wo = (const float*)d_in[6];
    float* out = (float*)d_out;

    __half *Q, *K, *Vt, *ATT, *Xh, *W6, *Wot;
    cudaGetSymbolAddress((void**)&Q,   g_Q);
    cudaGetSymbolAddress((void**)&K,   g_K);
    cudaGetSymbolAddress((void**)&Vt,  g_Vt);
    cudaGetSymbolAddress((void**)&ATT, g_attn);
    cudaGetSymbolAddress((void**)&Xh,  g_X);
    cudaGetSymbolAddress((void**)&W6,  g_W6);
    cudaGetSymbolAddress((void**)&Wot, g_Wo);

    cudaFuncSetAttribute(flash_f16,
        cudaFuncAttributeMaxDynamicSharedMemorySize, FLASH_SMEM);
    cudaFuncSetAttribute(gemm_f16,
        cudaFuncAttributeMaxDynamicSharedMemorySize, GEMM_SMEM);

    // 1) Mega-prep (one launch)
    prep_kernel<<<PREP_BLOCKS, 256>>>(x, wq, wk, wv, wo, Xh, W6, Wot);

    // 2) Fused QKV projection + RoPE (+ V transpose)
    gemm_f16<<<dim3(NQKV/128, S/128), 256, GEMM_SMEM>>>(
        S, NQKV, Dm, Xh, W6, nullptr, 1, Q, K, Vt, fc, fs);

    // 3) Causal GQA flash attention
    flash_f16<<<dim3(S/128, HQ), 256, FLASH_SMEM>>>(Q, K, Vt, ATT);

    // 4) Output projection (fp32 out)
    gemm_f16<<<dim3(Dm/128, S/128), 256, GEMM_SMEM>>>(
        S, Dm, NQ, ATT, Wot, out, 0, nullptr, nullptr, nullptr, nullptr, nullptr);
}